// round 8
// baseline (speedup 1.0000x reference)
#include <cuda_runtime.h>
#include <cuda_fp16.h>
#include <cstdint>

#define TOKENS 8192
#define DIN    4096
#define DOUT   4096
#define NFAC   2
#define RANK   64

// scratch (static __device__ globals; no allocation)
__device__ __half g_xh[(size_t)TOKENS * DIN];
__device__ __half g_weff[(size_t)DOUT * DIN];
__device__ __half g_abh[(size_t)DOUT * (NFAC * RANK)];
__device__ __half g_ch[(size_t)DIN * (NFAC * RANK)];

__device__ __forceinline__ uint32_t smem_u32(const void* p) {
    uint32_t a;
    asm("{ .reg .u64 t; cvta.to.shared.u64 t, %1; cvt.u32.u64 %0, t; }" : "=r"(a) : "l"(p));
    return a;
}
__device__ __forceinline__ void cp16(uint32_t dst, const void* src) {
    asm volatile("cp.async.cg.shared.global [%0], [%1], 16;" :: "r"(dst), "l"(src) : "memory");
}
#define SWZ(o) ((o) ^ (((o) >> 3) & 0x70))

__device__ __forceinline__ void ldsm4(uint32_t* r, uint32_t addr) {
    asm volatile("ldmatrix.sync.aligned.m8n8.x4.shared.b16 {%0,%1,%2,%3}, [%4];"
                 : "=r"(r[0]), "=r"(r[1]), "=r"(r[2]), "=r"(r[3]) : "r"(addr));
}
__device__ __forceinline__ void hmma(float* c, const uint32_t* a, uint32_t b0, uint32_t b1) {
    asm volatile(
        "mma.sync.aligned.m16n8k16.row.col.f32.f16.f16.f32 "
        "{%0,%1,%2,%3}, {%4,%5,%6,%7}, {%8,%9}, {%0,%1,%2,%3};"
        : "+f"(c[0]), "+f"(c[1]), "+f"(c[2]), "+f"(c[3])
        : "r"(a[0]), "r"(a[1]), "r"(a[2]), "r"(a[3]), "r"(b0), "r"(b1));
}

// abh[o, f*64+k] = fp16( sum_r tanh(A[f,o,r]) * B[f,r,k] )
__global__ void prep_ab(const float* __restrict__ As, const float* __restrict__ Bs,
                        __half* __restrict__ abh) {
    int o = blockIdx.x, f = blockIdx.y, k = threadIdx.x;
    __shared__ float ta[RANK];
    ta[k] = tanhf(As[((size_t)f * DOUT + o) * RANK + k]);
    __syncthreads();
    const float* Bf = Bs + (size_t)f * RANK * RANK;
    float acc = 0.f;
    #pragma unroll 8
    for (int r = 0; r < RANK; ++r) acc += ta[r] * Bf[r * RANK + k];
    abh[(size_t)o * (NFAC * RANK) + f * RANK + k] = __float2half_rn(acc);
}

// ch[i, f*64+k] = fp16( C[f,k,i] )
__global__ void conv_c(const float* __restrict__ Cs, __half* __restrict__ ch) {
    int idx = blockIdx.x * 256 + threadIdx.x;
    int i = idx & (DIN - 1);
    int fk = idx >> 12;
    ch[(size_t)i * (NFAC * RANK) + fk] = __float2half_rn(Cs[idx]);
}

__global__ void conv_x(const float4* __restrict__ xi, __half2* __restrict__ xo) {
    size_t i = (size_t)blockIdx.x * 256 + threadIdx.x;
    float4 v = xi[i];
    xo[2 * i]     = __floats2half2_rn(v.x, v.y);
    xo[2 * i + 1] = __floats2half2_rn(v.z, v.w);
}

// D[128x256] tile of A[M,K] @ B[N,K]^T, fp16 in / fp32 accum. 512 thr, warp tile 64x32.
// EPI 0: fp32 out, += bias[n].  EPI 1: fp16 out, += addv[m,n] (full matrix).
template<int KTOT, int EPI>
__global__ void __launch_bounds__(512, 1)
gemm_hmma(const __half* __restrict__ A, const __half* __restrict__ B,
          const float* __restrict__ addv, void* __restrict__ outp, int ldo)
{
    constexpr int BM = 128, BN = 256, BK = 64, S = 4;
    constexpr int NCH = KTOT / BK;
    constexpr int ABYTES = BM * 128;          // 16 KB
    constexpr int BBYTES = BN * 128;          // 32 KB
    constexpr int STAGE = ABYTES + BBYTES;    // 48 KB

    extern __shared__ char smraw[];
    uint32_t sbase = (smem_u32(smraw) + 1023) & ~1023u;

    const int tid = threadIdx.x, wid = tid >> 5, lane = tid & 31;
    const int wm = wid & 1, wn = wid >> 1;    // 2 x 8 warp grid, 64x32 per warp
    const int m0 = blockIdx.y * BM, n0 = blockIdx.x * BN;
    const __half* Ab = A + (size_t)m0 * KTOT;
    const __half* Bb = B + (size_t)n0 * KTOT;

    auto load_chunk = [&](int p) {
        uint32_t s = sbase + (p % S) * STAGE;
        const __half* Ap = Ab + p * BK;
        const __half* Bp = Bb + p * BK;
        #pragma unroll
        for (int it = 0; it < 2; ++it) {      // A: 128 rows x 8 segs = 1024 cp16
            int idx = tid + it * 512;
            int r = idx >> 3, sg = idx & 7;
            cp16(s + SWZ((uint32_t)(r * 128 + sg * 16)), Ap + (size_t)r * KTOT + sg * 8);
        }
        #pragma unroll
        for (int it = 0; it < 4; ++it) {      // B: 256 rows x 8 segs = 2048 cp16
            int idx = tid + it * 512;
            int r = idx >> 3, sg = idx & 7;
            cp16(s + ABYTES + SWZ((uint32_t)(r * 128 + sg * 16)),
                 Bp + (size_t)r * KTOT + sg * 8);
        }
    };

    float acc[4][4][4];
    #pragma unroll
    for (int t = 0; t < 4; ++t)
        #pragma unroll
        for (int j = 0; j < 4; ++j)
            #pragma unroll
            for (int q = 0; q < 4; ++q) acc[t][j][q] = 0.f;

    #pragma unroll
    for (int p = 0; p < S - 1; ++p) {
        if (p < NCH) load_chunk(p);
        asm volatile("cp.async.commit_group;" ::: "memory");
    }

    const int la = lane & 15, lb = lane >> 4;

    for (int c = 0; c < NCH; ++c) {
        asm volatile("cp.async.wait_group %0;" :: "n"(S - 2) : "memory");
        __syncthreads();
        int p = c + S - 1;
        if (p < NCH) load_chunk(p);
        asm volatile("cp.async.commit_group;" ::: "memory");

        uint32_t sA = sbase + (c % S) * STAGE;
        uint32_t sB = sA + ABYTES;
        #pragma unroll
        for (int ks = 0; ks < 4; ++ks) {      // K = 4 x 16
            uint32_t af[4][4], bf[2][4];
            #pragma unroll
            for (int t = 0; t < 4; ++t) {
                uint32_t row = (uint32_t)(wm * 64 + t * 16 + la);
                ldsm4(af[t], sA + SWZ(row * 128 + (uint32_t)(ks * 32 + lb * 16)));
            }
            #pragma unroll
            for (int u = 0; u < 2; ++u) {
                uint32_t row = (uint32_t)(wn * 32 + u * 16 + la);
                ldsm4(bf[u], sB + SWZ(row * 128 + (uint32_t)(ks * 32 + lb * 16)));
            }
            #pragma unroll
            for (int t = 0; t < 4; ++t)
                #pragma unroll
                for (int u = 0; u < 2; ++u) {
                    hmma(acc[t][2 * u],     af[t], bf[u][0], bf[u][2]);
                    hmma(acc[t][2 * u + 1], af[t], bf[u][1], bf[u][3]);
                }
        }
    }

    // epilogue (register accumulators -> global)
    const int r0 = lane >> 2, c0 = (lane & 3) * 2;
    #pragma unroll
    for (int t = 0; t < 4; ++t) {
        #pragma unroll
        for (int h = 0; h < 2; ++h) {
            size_t row = (size_t)(m0 + wm * 64 + t * 16 + h * 8 + r0);
            #pragma unroll
            for (int j = 0; j < 4; ++j) {
                int col = n0 + wn * 32 + j * 8 + c0;
                float v0 = acc[t][j][h * 2 + 0], v1 = acc[t][j][h * 2 + 1];
                if (EPI == 0) {
                    float2 w;
                    w.x = v0 + addv[col];
                    w.y = v1 + addv[col + 1];
                    *(float2*)((float*)outp + row * (size_t)ldo + col) = w;
                } else {
                    const float* wr = addv + row * (size_t)ldo + col;
                    *(__half2*)((__half*)outp + row * (size_t)ldo + col) =
                        __floats2half2_rn(v0 + wr[0], v1 + wr[1]);
                }
            }
        }
    }
}

extern "C" void kernel_launch(void* const* d_in, const int* in_sizes, int n_in,
                              void* d_out, int out_size) {
    (void)in_sizes; (void)n_in; (void)out_size;
    const float* x    = (const float*)d_in[0];
    const float* W    = (const float*)d_in[1];
    const float* bias = (const float*)d_in[2];
    const float* As   = (const float*)d_in[3];
    const float* Bs   = (const float*)d_in[4];
    const float* Cs   = (const float*)d_in[5];

    __half *xh, *weff, *abh, *ch;
    cudaGetSymbolAddress((void**)&xh,   g_xh);
    cudaGetSymbolAddress((void**)&weff, g_weff);
    cudaGetSymbolAddress((void**)&abh,  g_abh);
    cudaGetSymbolAddress((void**)&ch,   g_ch);

    const int SMEM_SZ = 1024 + 4 * (128 * 128 + 256 * 128);  // 197632 B
    cudaFuncSetAttribute(gemm_hmma<128, 1>,
                         cudaFuncAttributeMaxDynamicSharedMemorySize, SMEM_SZ);
    cudaFuncSetAttribute(gemm_hmma<4096, 0>,
                         cudaFuncAttributeMaxDynamicSharedMemorySize, SMEM_SZ);

    prep_ab<<<dim3(DOUT, NFAC), RANK>>>(As, Bs, abh);
    conv_c<<<(NFAC * RANK * DIN) / 256, 256>>>(Cs, ch);
    conv_x<<<(TOKENS * (DIN / 4)) / 256, 256>>>((const float4*)x, (__half2*)xh);
    // W_eff = W + abh @ ch^T   (M=DOUT, N=DIN, K=128), fp16 out
    gemm_hmma<128, 1><<<dim3(DIN / 256, DOUT / 128), 512, SMEM_SZ>>>(
        abh, ch, W, (void*)weff, DIN);
    // out = xh @ weff^T + bias (M=TOKENS, N=DOUT, K=DIN), fp32 out
    gemm_hmma<4096, 0><<<dim3(DOUT / 256, TOKENS / 128), 512, SMEM_SZ>>>(
        xh, weff, bias, d_out, DOUT);
}

// round 9
// speedup vs baseline: 1.0463x; 1.0463x over previous
#include <cuda_runtime.h>
#include <cuda_fp16.h>
#include <cstdint>

#define TOKENS 8192
#define DIN    4096
#define DOUT   4096
#define NFAC   2
#define RANK   64

// scratch (static __device__ globals; no allocation)
// xh: tiled A [mt(64)][kc(64)] blocks of 16KB (128 rows x 128B, swizzled)
// weff: tiled B [nt(16)][kc(64)] blocks of 32KB (256 rows x 128B, swizzled)
__device__ char g_xh[(size_t)TOKENS * DIN * 2];
__device__ char g_weff[(size_t)DOUT * DIN * 2];
__device__ __half g_abh[(size_t)DOUT * (NFAC * RANK)];
__device__ __half g_ch[(size_t)DIN * (NFAC * RANK)];

__device__ __forceinline__ uint32_t smem_u32(const void* p) {
    uint32_t a;
    asm("{ .reg .u64 t; cvta.to.shared.u64 t, %1; cvt.u32.u64 %0, t; }" : "=r"(a) : "l"(p));
    return a;
}
__device__ __forceinline__ void cp16(uint32_t dst, const void* src) {
    asm volatile("cp.async.cg.shared.global [%0], [%1], 16;" :: "r"(dst), "l"(src) : "memory");
}
__device__ __forceinline__ void bulkcp(uint32_t dst, const void* src, uint32_t bytes, uint32_t mbar) {
    asm volatile("cp.async.bulk.shared::cluster.global.mbarrier::complete_tx::bytes "
                 "[%0], [%1], %2, [%3];"
                 :: "r"(dst), "l"(src), "r"(bytes), "r"(mbar) : "memory");
}
__device__ __forceinline__ void expect_tx(uint32_t mbar, uint32_t bytes) {
    asm volatile("mbarrier.arrive.expect_tx.shared.b64 _, [%0], %1;"
                 :: "r"(mbar), "r"(bytes) : "memory");
}
__device__ __forceinline__ void mbar_wait(uint32_t a, uint32_t parity) {
    asm volatile(
        "{\n\t.reg .pred P;\n\tW%=:\n\t"
        "mbarrier.try_wait.parity.acquire.cta.shared::cta.b64 P, [%0], %1, 0x989680;\n\t"
        "@P bra.uni D%=;\n\tbra.uni W%=;\n\tD%=:\n\t}"
        :: "r"(a), "r"(parity) : "memory");
}
#define SWZ(o) ((o) ^ (((o) >> 3) & 0x70))

__device__ __forceinline__ void ldsm4(uint32_t* r, uint32_t addr) {
    asm volatile("ldmatrix.sync.aligned.m8n8.x4.shared.b16 {%0,%1,%2,%3}, [%4];"
                 : "=r"(r[0]), "=r"(r[1]), "=r"(r[2]), "=r"(r[3]) : "r"(addr));
}
__device__ __forceinline__ void hmma(float* c, const uint32_t* a, uint32_t b0, uint32_t b1) {
    asm volatile(
        "mma.sync.aligned.m16n8k16.row.col.f32.f16.f16.f32 "
        "{%0,%1,%2,%3}, {%4,%5,%6,%7}, {%8,%9}, {%0,%1,%2,%3};"
        : "+f"(c[0]), "+f"(c[1]), "+f"(c[2]), "+f"(c[3])
        : "r"(a[0]), "r"(a[1]), "r"(a[2]), "r"(a[3]), "r"(b0), "r"(b1));
}

// abh[o, f*64+k] = fp16( sum_r tanh(A[f,o,r]) * B[f,r,k] )
__global__ void prep_ab(const float* __restrict__ As, const float* __restrict__ Bs,
                        __half* __restrict__ abh) {
    int o = blockIdx.x, f = blockIdx.y, k = threadIdx.x;
    __shared__ float ta[RANK];
    ta[k] = tanhf(As[((size_t)f * DOUT + o) * RANK + k]);
    __syncthreads();
    const float* Bf = Bs + (size_t)f * RANK * RANK;
    float acc = 0.f;
    #pragma unroll 8
    for (int r = 0; r < RANK; ++r) acc += ta[r] * Bf[r * RANK + k];
    abh[(size_t)o * (NFAC * RANK) + f * RANK + k] = __float2half_rn(acc);
}

// ch[i, f*64+k] = fp16( C[f,k,i] )
__global__ void conv_c(const float* __restrict__ Cs, __half* __restrict__ ch) {
    int idx = blockIdx.x * 256 + threadIdx.x;
    int i = idx & (DIN - 1);
    int fk = idx >> 12;
    ch[(size_t)i * (NFAC * RANK) + fk] = __float2half_rn(Cs[idx]);
}

// x (fp32 row-major) -> xh tiled fp16: block (m>>7, i>>6), swizzled 128x128B
__global__ void conv_x(const float* __restrict__ xi, char* __restrict__ xo) {
    int idx = blockIdx.x * 256 + threadIdx.x;       // one 16B output segment each
    int m = idx >> 9, s = idx & 511, i = s << 3;
    const float4* p = (const float4*)(xi + (size_t)m * DIN + i);
    float4 a = p[0], b = p[1];
    uint4 v;
    ((__half2*)&v)[0] = __floats2half2_rn(a.x, a.y);
    ((__half2*)&v)[1] = __floats2half2_rn(a.z, a.w);
    ((__half2*)&v)[2] = __floats2half2_rn(b.x, b.y);
    ((__half2*)&v)[3] = __floats2half2_rn(b.z, b.w);
    size_t byte = (size_t)((m >> 7) * 64 + (i >> 6)) * 16384
                + SWZ((uint32_t)((m & 127) * 128 + (i & 63) * 2));
    *(uint4*)(xo + byte) = v;
}

// W_eff GEMM: weff[o,i] = W[o,i] + abh[o,:]@ch[i,:]^T, K=128. Output in TILED layout.
__global__ void __launch_bounds__(512, 1)
gemm_weff(const __half* __restrict__ A, const __half* __restrict__ B,
          const float* __restrict__ W, char* __restrict__ outp)
{
    constexpr int BM = 128, BN = 256, BK = 64, S = 4, KTOT = 128;
    constexpr int NCH = KTOT / BK;
    constexpr int ABYTES = BM * 128, BBYTES = BN * 128, STAGE = ABYTES + BBYTES;

    extern __shared__ char smraw[];
    uint32_t sbase = (smem_u32(smraw) + 1023) & ~1023u;

    const int tid = threadIdx.x, wid = tid >> 5, lane = tid & 31;
    const int wm = wid & 1, wn = wid >> 1;
    const int m0 = blockIdx.y * BM, n0 = blockIdx.x * BN;
    const __half* Ab = A + (size_t)m0 * KTOT;
    const __half* Bb = B + (size_t)n0 * KTOT;

    auto load_chunk = [&](int p) {
        uint32_t s = sbase + (p % S) * STAGE;
        const __half* Ap = Ab + p * BK;
        const __half* Bp = Bb + p * BK;
        #pragma unroll
        for (int it = 0; it < 2; ++it) {
            int idx = tid + it * 512;
            int r = idx >> 3, sg = idx & 7;
            cp16(s + SWZ((uint32_t)(r * 128 + sg * 16)), Ap + (size_t)r * KTOT + sg * 8);
        }
        #pragma unroll
        for (int it = 0; it < 4; ++it) {
            int idx = tid + it * 512;
            int r = idx >> 3, sg = idx & 7;
            cp16(s + ABYTES + SWZ((uint32_t)(r * 128 + sg * 16)),
                 Bp + (size_t)r * KTOT + sg * 8);
        }
    };

    float acc[4][4][4];
    #pragma unroll
    for (int t = 0; t < 4; ++t)
        #pragma unroll
        for (int j = 0; j < 4; ++j)
            #pragma unroll
            for (int q = 0; q < 4; ++q) acc[t][j][q] = 0.f;

    #pragma unroll
    for (int p = 0; p < S - 1; ++p) {
        if (p < NCH) load_chunk(p);
        asm volatile("cp.async.commit_group;" ::: "memory");
    }

    const int la = lane & 15, lb = lane >> 4;

    for (int c = 0; c < NCH; ++c) {
        asm volatile("cp.async.wait_group %0;" :: "n"(S - 2) : "memory");
        __syncthreads();
        int p = c + S - 1;
        if (p < NCH) load_chunk(p);
        asm volatile("cp.async.commit_group;" ::: "memory");

        uint32_t sA = sbase + (c % S) * STAGE;
        uint32_t sB = sA + ABYTES;
        #pragma unroll
        for (int ks = 0; ks < 4; ++ks) {
            uint32_t af[4][4], bf[2][4];
            #pragma unroll
            for (int t = 0; t < 4; ++t) {
                uint32_t row = (uint32_t)(wm * 64 + t * 16 + la);
                ldsm4(af[t], sA + SWZ(row * 128 + (uint32_t)(ks * 32 + lb * 16)));
            }
            #pragma unroll
            for (int u = 0; u < 2; ++u) {
                uint32_t row = (uint32_t)(wn * 32 + u * 16 + la);
                ldsm4(bf[u], sB + SWZ(row * 128 + (uint32_t)(ks * 32 + lb * 16)));
            }
            #pragma unroll
            for (int t = 0; t < 4; ++t)
                #pragma unroll
                for (int u = 0; u < 2; ++u) {
                    hmma(acc[t][2 * u],     af[t], bf[u][0], bf[u][2]);
                    hmma(acc[t][2 * u + 1], af[t], bf[u][1], bf[u][3]);
                }
        }
    }

    // epilogue: += W, write fp16 into TILED+swizzled weff layout
    const int r0 = lane >> 2, c0 = (lane & 3) * 2;
    #pragma unroll
    for (int t = 0; t < 4; ++t) {
        #pragma unroll
        for (int h = 0; h < 2; ++h) {
            int o = m0 + wm * 64 + t * 16 + h * 8 + r0;
            #pragma unroll
            for (int j = 0; j < 4; ++j) {
                int i = n0 + wn * 32 + j * 8 + c0;
                const float* wr = W + (size_t)o * DIN + i;
                __half2 hv = __floats2half2_rn(acc[t][j][h * 2 + 0] + wr[0],
                                               acc[t][j][h * 2 + 1] + wr[1]);
                size_t byte = (size_t)((o >> 8) * 64 + (i >> 6)) * 32768
                            + SWZ((uint32_t)((o & 255) * 128 + (i & 63) * 2));
                *(__half2*)(outp + byte) = hv;
            }
        }
    }
}

// Big GEMM: out[m,n] = xh[m,:] @ weff[n,:]^T + bias[n], fp32 out.
// A/B tiles are contiguous pre-swizzled blocks -> 2 cp.async.bulk per chunk.
__global__ void __launch_bounds__(512, 1)
gemm_big(const char* __restrict__ At, const char* __restrict__ Bt,
         const float* __restrict__ bias, float* __restrict__ outp)
{
    constexpr int BM = 128, BN = 256, S = 4, NCH = 64;
    constexpr int ABYTES = 16384, BBYTES = 32768, STAGE = ABYTES + BBYTES;

    extern __shared__ char smraw[];
    uint32_t sbase = (smem_u32(smraw) + 1023) & ~1023u;
    uint32_t mbar  = sbase;               // 4 x 8B mbarriers
    uint32_t tiles = sbase + 1024;

    const int tid = threadIdx.x, wid = tid >> 5, lane = tid & 31;
    const int wm = wid & 1, wn = wid >> 1;
    const int mt = blockIdx.y, nt = blockIdx.x;
    const int m0 = mt * BM, n0 = nt * BN;

    if (tid == 0) {
        #pragma unroll
        for (int s = 0; s < S; s++)
            asm volatile("mbarrier.init.shared.b64 [%0], 1;" :: "r"(mbar + s * 8) : "memory");
        asm volatile("fence.proxy.async.shared::cta;" ::: "memory");
    }
    __syncthreads();

    if (tid == 0) {
        #pragma unroll
        for (int p = 0; p < S - 1; ++p) {
            uint32_t mb = mbar + p * 8;
            expect_tx(mb, STAGE);
            bulkcp(tiles + p * STAGE,          At + (size_t)(mt * 64 + p) * ABYTES, ABYTES, mb);
            bulkcp(tiles + p * STAGE + ABYTES, Bt + (size_t)(nt * 64 + p) * BBYTES, BBYTES, mb);
        }
    }

    float acc[4][4][4];
    #pragma unroll
    for (int t = 0; t < 4; ++t)
        #pragma unroll
        for (int j = 0; j < 4; ++j)
            #pragma unroll
            for (int q = 0; q < 4; ++q) acc[t][j][q] = 0.f;

    const int la = lane & 15, lb = lane >> 4;

    for (int c = 0; c < NCH; ++c) {
        if (tid == 0) {
            int p = c + S - 1;
            if (p < NCH) {
                uint32_t mb = mbar + (p % S) * 8;
                expect_tx(mb, STAGE);
                bulkcp(tiles + (p % S) * STAGE,          At + (size_t)(mt * 64 + p) * ABYTES, ABYTES, mb);
                bulkcp(tiles + (p % S) * STAGE + ABYTES, Bt + (size_t)(nt * 64 + p) * BBYTES, BBYTES, mb);
            }
        }
        mbar_wait(mbar + (c % S) * 8, (uint32_t)((c / S) & 1));

        uint32_t sA = tiles + (c % S) * STAGE;
        uint32_t sB = sA + ABYTES;
        #pragma unroll
        for (int ks = 0; ks < 4; ++ks) {
            uint32_t af[4][4], bf[2][4];
            #pragma unroll
            for (int t = 0; t < 4; ++t) {
                uint32_t row = (uint32_t)(wm * 64 + t * 16 + la);
                ldsm4(af[t], sA + SWZ(row * 128 + (uint32_t)(ks * 32 + lb * 16)));
            }
            #pragma unroll
            for (int u = 0; u < 2; ++u) {
                uint32_t row = (uint32_t)(wn * 32 + u * 16 + la);
                ldsm4(bf[u], sB + SWZ(row * 128 + (uint32_t)(ks * 32 + lb * 16)));
            }
            #pragma unroll
            for (int t = 0; t < 4; ++t)
                #pragma unroll
                for (int u = 0; u < 2; ++u) {
                    hmma(acc[t][2 * u],     af[t], bf[u][0], bf[u][2]);
                    hmma(acc[t][2 * u + 1], af[t], bf[u][1], bf[u][3]);
                }
        }
        __syncthreads();   // all warps done with stage c%S before tid0 refills it
    }

    // epilogue: fp32 out += bias
    const int r0 = lane >> 2, c0 = (lane & 3) * 2;
    #pragma unroll
    for (int t = 0; t < 4; ++t) {
        #pragma unroll
        for (int h = 0; h < 2; ++h) {
            size_t row = (size_t)(m0 + wm * 64 + t * 16 + h * 8 + r0);
            #pragma unroll
            for (int j = 0; j < 4; ++j) {
                int col = n0 + wn * 32 + j * 8 + c0;
                float2 w;
                w.x = acc[t][j][h * 2 + 0] + bias[col];
                w.y = acc[t][j][h * 2 + 1] + bias[col + 1];
                *(float2*)(outp + row * DOUT + col) = w;
            }
        }
    }
}

extern "C" void kernel_launch(void* const* d_in, const int* in_sizes, int n_in,
                              void* d_out, int out_size) {
    (void)in_sizes; (void)n_in; (void)out_size;
    const float* x    = (const float*)d_in[0];
    const float* W    = (const float*)d_in[1];
    const float* bias = (const float*)d_in[2];
    const float* As   = (const float*)d_in[3];
    const float* Bs   = (const float*)d_in[4];
    const float* Cs   = (const float*)d_in[5];

    char *xh, *weff;
    __half *abh, *ch;
    cudaGetSymbolAddress((void**)&xh,   g_xh);
    cudaGetSymbolAddress((void**)&weff, g_weff);
    cudaGetSymbolAddress((void**)&abh,  g_abh);
    cudaGetSymbolAddress((void**)&ch,   g_ch);

    const int SMEM_SZ = 1024 + 4 * (128 * 128 + 256 * 128);  // 197632 B
    cudaFuncSetAttribute(gemm_weff,
                         cudaFuncAttributeMaxDynamicSharedMemorySize, SMEM_SZ);
    cudaFuncSetAttribute(gemm_big,
                         cudaFuncAttributeMaxDynamicSharedMemorySize, SMEM_SZ);

    prep_ab<<<dim3(DOUT, NFAC), RANK>>>(As, Bs, abh);
    conv_c<<<(NFAC * RANK * DIN) / 256, 256>>>(Cs, ch);
    conv_x<<<(TOKENS * DIN / 8) / 256, 256>>>(x, xh);
    // W_eff (tiled+swizzled fp16) = W + abh @ ch^T
    gemm_weff<<<dim3(DIN / 256, DOUT / 128), 512, SMEM_SZ>>>(abh, ch, W, weff);
    // out = xh @ weff^T + bias
    gemm_big<<<dim3(DOUT / 256, TOKENS / 128), 512, SMEM_SZ>>>(xh, weff, bias, (float*)d_out);
}

// round 11
// speedup vs baseline: 1.0657x; 1.0185x over previous
#include <cuda_runtime.h>
#include <cuda_fp16.h>
#include <cstdint>

#define TOKENS 8192
#define DIN    4096
#define DOUT   4096
#define NFAC   2
#define RANK   64

// scratch (static __device__ globals; no allocation)
// xh: tiled A [mt(64)][kc(64)] blocks of 16KB (128 rows x 128B, swizzled)
// weff: tiled B [nt(16)][kc(64)] blocks of 32KB (256 rows x 128B, swizzled)
__device__ char g_xh[(size_t)TOKENS * DIN * 2];
__device__ char g_weff[(size_t)DOUT * DIN * 2];
__device__ __half g_abh[(size_t)DOUT * (NFAC * RANK)];
__device__ __half g_ch[(size_t)DIN * (NFAC * RANK)];

__device__ __forceinline__ uint32_t smem_u32(const void* p) {
    uint32_t a;
    asm("{ .reg .u64 t; cvta.to.shared.u64 t, %1; cvt.u32.u64 %0, t; }" : "=r"(a) : "l"(p));
    return a;
}
__device__ __forceinline__ void cp16(uint32_t dst, const void* src) {
    asm volatile("cp.async.cg.shared.global [%0], [%1], 16;" :: "r"(dst), "l"(src) : "memory");
}
__device__ __forceinline__ void bulkcp(uint32_t dst, const void* src, uint32_t bytes, uint32_t mbar) {
    asm volatile("cp.async.bulk.shared::cluster.global.mbarrier::complete_tx::bytes "
                 "[%0], [%1], %2, [%3];"
                 :: "r"(dst), "l"(src), "r"(bytes), "r"(mbar) : "memory");
}
__device__ __forceinline__ void expect_tx(uint32_t mbar, uint32_t bytes) {
    asm volatile("mbarrier.arrive.expect_tx.shared.b64 _, [%0], %1;"
                 :: "r"(mbar), "r"(bytes) : "memory");
}
__device__ __forceinline__ void mbar_wait(uint32_t a, uint32_t parity) {
    asm volatile(
        "{\n\t.reg .pred P;\n\tW%=:\n\t"
        "mbarrier.try_wait.parity.acquire.cta.shared::cta.b64 P, [%0], %1, 0x989680;\n\t"
        "@P bra.uni D%=;\n\tbra.uni W%=;\n\tD%=:\n\t}"
        :: "r"(a), "r"(parity) : "memory");
}
#define SWZ(o) ((o) ^ (((o) >> 3) & 0x70))

__device__ __forceinline__ void ldsm4(uint32_t* r, uint32_t addr) {
    asm volatile("ldmatrix.sync.aligned.m8n8.x4.shared.b16 {%0,%1,%2,%3}, [%4];"
                 : "=r"(r[0]), "=r"(r[1]), "=r"(r[2]), "=r"(r[3]) : "r"(addr));
}
__device__ __forceinline__ void hmma(float* c, const uint32_t* a, uint32_t b0, uint32_t b1) {
    asm volatile(
        "mma.sync.aligned.m16n8k16.row.col.f32.f16.f16.f32 "
        "{%0,%1,%2,%3}, {%4,%5,%6,%7}, {%8,%9}, {%0,%1,%2,%3};"
        : "+f"(c[0]), "+f"(c[1]), "+f"(c[2]), "+f"(c[3])
        : "r"(a[0]), "r"(a[1]), "r"(a[2]), "r"(a[3]), "r"(b0), "r"(b1));
}

// abh[o, f*64+k] = fp16( sum_r tanh(A[f,o,r]) * B[f,r,k] )
__global__ void prep_ab(const float* __restrict__ As, const float* __restrict__ Bs,
                        __half* __restrict__ abh) {
    int o = blockIdx.x, f = blockIdx.y, k = threadIdx.x;
    __shared__ float ta[RANK];
    ta[k] = tanhf(As[((size_t)f * DOUT + o) * RANK + k]);
    __syncthreads();
    const float* Bf = Bs + (size_t)f * RANK * RANK;
    float acc = 0.f;
    #pragma unroll 8
    for (int r = 0; r < RANK; ++r) acc += ta[r] * Bf[r * RANK + k];
    abh[(size_t)o * (NFAC * RANK) + f * RANK + k] = __float2half_rn(acc);
}

// ch[i, f*64+k] = fp16( C[f,k,i] )
__global__ void conv_c(const float* __restrict__ Cs, __half* __restrict__ ch) {
    int idx = blockIdx.x * 256 + threadIdx.x;
    int i = idx & (DIN - 1);
    int fk = idx >> 12;
    ch[(size_t)i * (NFAC * RANK) + fk] = __float2half_rn(Cs[idx]);
}

// x (fp32 row-major) -> xh tiled fp16: block (m>>7, i>>6), swizzled 128x128B
__global__ void conv_x(const float* __restrict__ xi, char* __restrict__ xo) {
    int idx = blockIdx.x * 256 + threadIdx.x;       // one 16B output segment each
    int m = idx >> 9, s = idx & 511, i = s << 3;
    const float4* p = (const float4*)(xi + (size_t)m * DIN + i);
    float4 a = p[0], b = p[1];
    uint4 v;
    ((__half2*)&v)[0] = __floats2half2_rn(a.x, a.y);
    ((__half2*)&v)[1] = __floats2half2_rn(a.z, a.w);
    ((__half2*)&v)[2] = __floats2half2_rn(b.x, b.y);
    ((__half2*)&v)[3] = __floats2half2_rn(b.z, b.w);
    size_t byte = (size_t)((m >> 7) * 64 + (i >> 6)) * 16384
                + SWZ((uint32_t)((m & 127) * 128 + (i & 63) * 2));
    *(uint4*)(xo + byte) = v;
}

// W_eff GEMM: weff[o,i] = W[o,i] + abh[o,:]@ch[i,:]^T, K=128. Output in TILED layout.
__global__ void __launch_bounds__(512, 1)
gemm_weff(const __half* __restrict__ A, const __half* __restrict__ B,
          const float* __restrict__ W, char* __restrict__ outp)
{
    constexpr int BM = 128, BN = 256, BK = 64, S = 2, KTOT = 128;
    constexpr int NCH = KTOT / BK;
    constexpr int ABYTES = BM * 128, BBYTES = BN * 128, STAGE = ABYTES + BBYTES;

    extern __shared__ char smraw[];
    uint32_t sbase = (smem_u32(smraw) + 1023) & ~1023u;

    const int tid = threadIdx.x, wid = tid >> 5, lane = tid & 31;
    const int wm = wid & 1, wn = wid >> 1;
    const int m0 = blockIdx.y * BM, n0 = blockIdx.x * BN;
    const __half* Ab = A + (size_t)m0 * KTOT;
    const __half* Bb = B + (size_t)n0 * KTOT;

    auto load_chunk = [&](int p) {
        uint32_t s = sbase + (p % S) * STAGE;
        const __half* Ap = Ab + p * BK;
        const __half* Bp = Bb + p * BK;
        #pragma unroll
        for (int it = 0; it < 2; ++it) {
            int idx = tid + it * 512;
            int r = idx >> 3, sg = idx & 7;
            cp16(s + SWZ((uint32_t)(r * 128 + sg * 16)), Ap + (size_t)r * KTOT + sg * 8);
        }
        #pragma unroll
        for (int it = 0; it < 4; ++it) {
            int idx = tid + it * 512;
            int r = idx >> 3, sg = idx & 7;
            cp16(s + ABYTES + SWZ((uint32_t)(r * 128 + sg * 16)),
                 Bp + (size_t)r * KTOT + sg * 8);
        }
    };

    float acc[4][4][4];
    #pragma unroll
    for (int t = 0; t < 4; ++t)
        #pragma unroll
        for (int j = 0; j < 4; ++j)
            #pragma unroll
            for (int q = 0; q < 4; ++q) acc[t][j][q] = 0.f;

    load_chunk(0);
    asm volatile("cp.async.commit_group;" ::: "memory");
    load_chunk(1);
    asm volatile("cp.async.commit_group;" ::: "memory");

    const int la = lane & 15, lb = lane >> 4;

    #pragma unroll
    for (int c = 0; c < NCH; ++c) {
        if (c < NCH - 1)
            asm volatile("cp.async.wait_group 1;" ::: "memory");
        else
            asm volatile("cp.async.wait_group 0;" ::: "memory");
        __syncthreads();
        uint32_t sA = sbase + (c % S) * STAGE;
        uint32_t sB = sA + ABYTES;
        #pragma unroll
        for (int ks = 0; ks < 4; ++ks) {
            uint32_t af[4][4], bf[2][4];
            #pragma unroll
            for (int t = 0; t < 4; ++t) {
                uint32_t row = (uint32_t)(wm * 64 + t * 16 + la);
                ldsm4(af[t], sA + SWZ(row * 128 + (uint32_t)(ks * 32 + lb * 16)));
            }
            #pragma unroll
            for (int u = 0; u < 2; ++u) {
                uint32_t row = (uint32_t)(wn * 32 + u * 16 + la);
                ldsm4(bf[u], sB + SWZ(row * 128 + (uint32_t)(ks * 32 + lb * 16)));
            }
            #pragma unroll
            for (int t = 0; t < 4; ++t)
                #pragma unroll
                for (int u = 0; u < 2; ++u) {
                    hmma(acc[t][2 * u],     af[t], bf[u][0], bf[u][2]);
                    hmma(acc[t][2 * u + 1], af[t], bf[u][1], bf[u][3]);
                }
        }
    }

    // epilogue: += W, write fp16 into TILED+swizzled weff layout
    const int r0 = lane >> 2, c0 = (lane & 3) * 2;
    #pragma unroll
    for (int t = 0; t < 4; ++t) {
        #pragma unroll
        for (int h = 0; h < 2; ++h) {
            int o = m0 + wm * 64 + t * 16 + h * 8 + r0;
            #pragma unroll
            for (int j = 0; j < 4; ++j) {
                int i = n0 + wn * 32 + j * 8 + c0;
                const float* wr = W + (size_t)o * DIN + i;
                __half2 hv = __floats2half2_rn(acc[t][j][h * 2 + 0] + wr[0],
                                               acc[t][j][h * 2 + 1] + wr[1]);
                size_t byte = (size_t)((o >> 8) * 64 + (i >> 6)) * 32768
                            + SWZ((uint32_t)((o & 255) * 128 + (i & 63) * 2));
                *(__half2*)(outp + byte) = hv;
            }
        }
    }
}

// Big GEMM: out[m,n] = xh[m,:] @ weff[n,:]^T + bias[n], fp32 out.
// BK=128 chunks (2 adjacent 64-K blocks = contiguous): 1 A-bulk (32KB) + 1 B-bulk (64KB)
// per chunk, S=2 stages of 96KB.
__global__ void __launch_bounds__(512, 1)
gemm_big(const char* __restrict__ At, const char* __restrict__ Bt,
         const float* __restrict__ bias, float* __restrict__ outp)
{
    constexpr int BM = 128, BN = 256, S = 2, NCH = 32;   // BK = 128
    constexpr int ABLK = 16384, BBLK = 32768;            // per-64K-block bytes
    constexpr int ABYTES = 2 * ABLK, BBYTES = 2 * BBLK;  // per chunk: 32KB + 64KB
    constexpr int STAGE = ABYTES + BBYTES;               // 96KB

    extern __shared__ char smraw[];
    uint32_t sbase = (smem_u32(smraw) + 1023) & ~1023u;
    uint32_t mbar  = sbase;               // 2 x 8B mbarriers
    uint32_t tiles = sbase + 1024;

    const int tid = threadIdx.x, wid = tid >> 5, lane = tid & 31;
    const int wm = wid & 1, wn = wid >> 1;
    const int mt = blockIdx.y, nt = blockIdx.x;
    const int m0 = mt * BM, n0 = nt * BN;

    if (tid == 0) {
        #pragma unroll
        for (int s = 0; s < S; s++)
            asm volatile("mbarrier.init.shared.b64 [%0], 1;" :: "r"(mbar + s * 8) : "memory");
        asm volatile("fence.proxy.async.shared::cta;" ::: "memory");
    }
    __syncthreads();

    auto issue = [&](int p) {   // tid0 only
        uint32_t mb = mbar + (p & 1) * 8;
        uint32_t st = tiles + (p & 1) * STAGE;
        expect_tx(mb, STAGE);
        bulkcp(st,          At + (size_t)(mt * 64 + 2 * p) * ABLK, ABYTES, mb);
        bulkcp(st + ABYTES, Bt + (size_t)(nt * 64 + 2 * p) * BBLK, BBYTES, mb);
    };

    if (tid == 0) issue(0);

    float acc[4][4][4];
    #pragma unroll
    for (int t = 0; t < 4; ++t)
        #pragma unroll
        for (int j = 0; j < 4; ++j)
            #pragma unroll
            for (int q = 0; q < 4; ++q) acc[t][j][q] = 0.f;

    const int la = lane & 15, lb = lane >> 4;

    for (int c = 0; c < NCH; ++c) {
        // refill the other stage (free at c==0; else freed by last iter's syncthreads)
        if (tid == 0 && c + 1 < NCH) issue(c + 1);
        mbar_wait(mbar + (c & 1) * 8, (uint32_t)((c >> 1) & 1));

        uint32_t sA = tiles + (c & 1) * STAGE;
        uint32_t sB = sA + ABYTES;
        #pragma unroll
        for (int ks = 0; ks < 8; ++ks) {          // 8 x K16 per BK=128 chunk
            uint32_t af[4][4], bf[2][4];
            #pragma unroll
            for (int t = 0; t < 4; ++t) {
                uint32_t row = (uint32_t)(wm * 64 + t * 16 + la);
                ldsm4(af[t], sA + (uint32_t)(ks >> 2) * ABLK
                            + SWZ(row * 128 + (uint32_t)((ks & 3) * 32 + lb * 16)));
            }
            #pragma unroll
            for (int u = 0; u < 2; ++u) {
                uint32_t row = (uint32_t)(wn * 32 + u * 16 + la);
                ldsm4(bf[u], sB + (uint32_t)(ks >> 2) * BBLK
                            + SWZ(row * 128 + (uint32_t)((ks & 3) * 32 + lb * 16)));
            }
            #pragma unroll
            for (int t = 0; t < 4; ++t)
                #pragma unroll
                for (int u = 0; u < 2; ++u) {
                    hmma(acc[t][2 * u],     af[t], bf[u][0], bf[u][2]);
                    hmma(acc[t][2 * u + 1], af[t], bf[u][1], bf[u][3]);
                }
        }
        __syncthreads();   // all warps done with stage c&1 before it is refilled
    }

    // epilogue: fp32 out += bias
    const int r0 = lane >> 2, c0 = (lane & 3) * 2;
    #pragma unroll
    for (int t = 0; t < 4; ++t) {
        #pragma unroll
        for (int h = 0; h < 2; ++h) {
            size_t row = (size_t)(m0 + wm * 64 + t * 16 + h * 8 + r0);
            #pragma unroll
            for (int j = 0; j < 4; ++j) {
                int col = n0 + wn * 32 + j * 8 + c0;
                float2 w;
                w.x = acc[t][j][h * 2 + 0] + bias[col];
                w.y = acc[t][j][h * 2 + 1] + bias[col + 1];
                *(float2*)(outp + row * DOUT + col) = w;
            }
        }
    }
}

extern "C" void kernel_launch(void* const* d_in, const int* in_sizes, int n_in,
                              void* d_out, int out_size) {
    (void)in_sizes; (void)n_in; (void)out_size;
    const float* x    = (const float*)d_in[0];
    const float* W    = (const float*)d_in[1];
    const float* bias = (const float*)d_in[2];
    const float* As   = (const float*)d_in[3];
    const float* Bs   = (const float*)d_in[4];
    const float* Cs   = (const float*)d_in[5];

    char *xh, *weff;
    __half *abh, *ch;
    cudaGetSymbolAddress((void**)&xh,   g_xh);
    cudaGetSymbolAddress((void**)&weff, g_weff);
    cudaGetSymbolAddress((void**)&abh,  g_abh);
    cudaGetSymbolAddress((void**)&ch,   g_ch);

    const int SMEM_WEFF = 1024 + 2 * (128 * 128 + 256 * 128);  // 99328 B
    const int SMEM_BIG  = 1024 + 2 * (32768 + 65536);          // 197632 B
    cudaFuncSetAttribute(gemm_weff,
                         cudaFuncAttributeMaxDynamicSharedMemorySize, SMEM_WEFF);
    cudaFuncSetAttribute(gemm_big,
                         cudaFuncAttributeMaxDynamicSharedMemorySize, SMEM_BIG);

    prep_ab<<<dim3(DOUT, NFAC), RANK>>>(As, Bs, abh);
    conv_c<<<(NFAC * RANK * DIN) / 256, 256>>>(Cs, ch);
    conv_x<<<(TOKENS * DIN / 8) / 256, 256>>>(x, xh);
    // W_eff (tiled+swizzled fp16) = W + abh @ ch^T
    gemm_weff<<<dim3(DIN / 256, DOUT / 128), 512, SMEM_WEFF>>>(abh, ch, W, weff);
    // out = xh @ weff^T + bias
    gemm_big<<<dim3(DOUT / 256, TOKENS / 128), 512, SMEM_BIG>>>(xh, weff, bias, (float*)d_out);
}

// round 12
// speedup vs baseline: 1.1038x; 1.0358x over previous
#include <cuda_runtime.h>
#include <cuda_fp16.h>
#include <cstdint>

#define TOKENS 8192
#define DIN    4096
#define DOUT   4096
#define NFAC   2
#define RANK   64

// scratch (static __device__ globals; no allocation)
// xh: tiled A [mt(64)][kc(64)] blocks of 16KB (128 rows x 128B, swizzled)
// weff: tiled B [nt(16)][kc(64)] blocks of 32KB (256 rows x 128B, swizzled)
__device__ char g_xh[(size_t)TOKENS * DIN * 2];
__device__ char g_weff[(size_t)DOUT * DIN * 2];
__device__ __half g_abh[(size_t)DOUT * (NFAC * RANK)];
__device__ __half g_ch[(size_t)DIN * (NFAC * RANK)];

__device__ __forceinline__ uint32_t smem_u32(const void* p) {
    uint32_t a;
    asm("{ .reg .u64 t; cvta.to.shared.u64 t, %1; cvt.u32.u64 %0, t; }" : "=r"(a) : "l"(p));
    return a;
}
__device__ __forceinline__ void cp16(uint32_t dst, const void* src) {
    asm volatile("cp.async.cg.shared.global [%0], [%1], 16;" :: "r"(dst), "l"(src) : "memory");
}
__device__ __forceinline__ void bulkcp(uint32_t dst, const void* src, uint32_t bytes, uint32_t mbar) {
    asm volatile("cp.async.bulk.shared::cluster.global.mbarrier::complete_tx::bytes "
                 "[%0], [%1], %2, [%3];"
                 :: "r"(dst), "l"(src), "r"(bytes), "r"(mbar) : "memory");
}
__device__ __forceinline__ void expect_tx(uint32_t mbar, uint32_t bytes) {
    asm volatile("mbarrier.arrive.expect_tx.shared.b64 _, [%0], %1;"
                 :: "r"(mbar), "r"(bytes) : "memory");
}
__device__ __forceinline__ void mbar_wait(uint32_t a, uint32_t parity) {
    asm volatile(
        "{\n\t.reg .pred P;\n\tW%=:\n\t"
        "mbarrier.try_wait.parity.acquire.cta.shared::cta.b64 P, [%0], %1, 0x989680;\n\t"
        "@P bra.uni D%=;\n\tbra.uni W%=;\n\tD%=:\n\t}"
        :: "r"(a), "r"(parity) : "memory");
}
#define SWZ(o) ((o) ^ (((o) >> 3) & 0x70))

__device__ __forceinline__ void ldsm4(uint32_t* r, uint32_t addr) {
    asm volatile("ldmatrix.sync.aligned.m8n8.x4.shared.b16 {%0,%1,%2,%3}, [%4];"
                 : "=r"(r[0]), "=r"(r[1]), "=r"(r[2]), "=r"(r[3]) : "r"(addr));
}
__device__ __forceinline__ void hmma(float* c, const uint32_t* a, uint32_t b0, uint32_t b1) {
    asm volatile(
        "mma.sync.aligned.m16n8k16.row.col.f32.f16.f16.f32 "
        "{%0,%1,%2,%3}, {%4,%5,%6,%7}, {%8,%9}, {%0,%1,%2,%3};"
        : "+f"(c[0]), "+f"(c[1]), "+f"(c[2]), "+f"(c[3])
        : "r"(a[0]), "r"(a[1]), "r"(a[2]), "r"(a[3]), "r"(b0), "r"(b1));
}

// abh[o, f*64+k] = fp16( sum_r tanh(A[f,o,r]) * B[f,r,k] )
__global__ void prep_ab(const float* __restrict__ As, const float* __restrict__ Bs,
                        __half* __restrict__ abh) {
    int o = blockIdx.x, f = blockIdx.y, k = threadIdx.x;
    __shared__ float ta[RANK];
    ta[k] = tanhf(As[((size_t)f * DOUT + o) * RANK + k]);
    __syncthreads();
    const float* Bf = Bs + (size_t)f * RANK * RANK;
    float acc = 0.f;
    #pragma unroll 8
    for (int r = 0; r < RANK; ++r) acc += ta[r] * Bf[r * RANK + k];
    abh[(size_t)o * (NFAC * RANK) + f * RANK + k] = __float2half_rn(acc);
}

// ch[i, f*64+k] = fp16( C[f,k,i] )
__global__ void conv_c(const float* __restrict__ Cs, __half* __restrict__ ch) {
    int idx = blockIdx.x * 256 + threadIdx.x;
    int i = idx & (DIN - 1);
    int fk = idx >> 12;
    ch[(size_t)i * (NFAC * RANK) + fk] = __float2half_rn(Cs[idx]);
}

// x (fp32 row-major) -> xh tiled fp16: block (m>>7, i>>6), swizzled 128x128B
__global__ void conv_x(const float* __restrict__ xi, char* __restrict__ xo) {
    int idx = blockIdx.x * 256 + threadIdx.x;       // one 16B output segment each
    int m = idx >> 9, s = idx & 511, i = s << 3;
    const float4* p = (const float4*)(xi + (size_t)m * DIN + i);
    float4 a = p[0], b = p[1];
    uint4 v;
    ((__half2*)&v)[0] = __floats2half2_rn(a.x, a.y);
    ((__half2*)&v)[1] = __floats2half2_rn(a.z, a.w);
    ((__half2*)&v)[2] = __floats2half2_rn(b.x, b.y);
    ((__half2*)&v)[3] = __floats2half2_rn(b.z, b.w);
    size_t byte = (size_t)((m >> 7) * 64 + (i >> 6)) * 16384
                + SWZ((uint32_t)((m & 127) * 128 + (i & 63) * 2));
    *(uint4*)(xo + byte) = v;
}

// W_eff GEMM: weff[o,i] = W[o,i] + abh[o,:]@ch[i,:]^T, K=128. Output in TILED layout.
__global__ void __launch_bounds__(512, 1)
gemm_weff(const __half* __restrict__ A, const __half* __restrict__ B,
          const float* __restrict__ W, char* __restrict__ outp)
{
    constexpr int BM = 128, BN = 256, BK = 64, S = 2, KTOT = 128;
    constexpr int NCH = KTOT / BK;
    constexpr int ABYTES = BM * 128, BBYTES = BN * 128, STAGE = ABYTES + BBYTES;

    extern __shared__ char smraw[];
    uint32_t sbase = (smem_u32(smraw) + 1023) & ~1023u;

    const int tid = threadIdx.x, wid = tid >> 5, lane = tid & 31;
    const int wm = wid & 1, wn = wid >> 1;
    const int m0 = blockIdx.y * BM, n0 = blockIdx.x * BN;
    const __half* Ab = A + (size_t)m0 * KTOT;
    const __half* Bb = B + (size_t)n0 * KTOT;

    auto load_chunk = [&](int p) {
        uint32_t s = sbase + (p % S) * STAGE;
        const __half* Ap = Ab + p * BK;
        const __half* Bp = Bb + p * BK;
        #pragma unroll
        for (int it = 0; it < 2; ++it) {
            int idx = tid + it * 512;
            int r = idx >> 3, sg = idx & 7;
            cp16(s + SWZ((uint32_t)(r * 128 + sg * 16)), Ap + (size_t)r * KTOT + sg * 8);
        }
        #pragma unroll
        for (int it = 0; it < 4; ++it) {
            int idx = tid + it * 512;
            int r = idx >> 3, sg = idx & 7;
            cp16(s + ABYTES + SWZ((uint32_t)(r * 128 + sg * 16)),
                 Bp + (size_t)r * KTOT + sg * 8);
        }
    };

    float acc[4][4][4];
    #pragma unroll
    for (int t = 0; t < 4; ++t)
        #pragma unroll
        for (int j = 0; j < 4; ++j)
            #pragma unroll
            for (int q = 0; q < 4; ++q) acc[t][j][q] = 0.f;

    load_chunk(0);
    asm volatile("cp.async.commit_group;" ::: "memory");
    load_chunk(1);
    asm volatile("cp.async.commit_group;" ::: "memory");

    const int la = lane & 15, lb = lane >> 4;

    #pragma unroll
    for (int c = 0; c < NCH; ++c) {
        if (c < NCH - 1)
            asm volatile("cp.async.wait_group 1;" ::: "memory");
        else
            asm volatile("cp.async.wait_group 0;" ::: "memory");
        __syncthreads();
        uint32_t sA = sbase + (c % S) * STAGE;
        uint32_t sB = sA + ABYTES;
        #pragma unroll
        for (int ks = 0; ks < 4; ++ks) {
            uint32_t af[4][4], bf[2][4];
            #pragma unroll
            for (int t = 0; t < 4; ++t) {
                uint32_t row = (uint32_t)(wm * 64 + t * 16 + la);
                ldsm4(af[t], sA + SWZ(row * 128 + (uint32_t)(ks * 32 + lb * 16)));
            }
            #pragma unroll
            for (int u = 0; u < 2; ++u) {
                uint32_t row = (uint32_t)(wn * 32 + u * 16 + la);
                ldsm4(bf[u], sB + SWZ(row * 128 + (uint32_t)(ks * 32 + lb * 16)));
            }
            #pragma unroll
            for (int t = 0; t < 4; ++t)
                #pragma unroll
                for (int u = 0; u < 2; ++u) {
                    hmma(acc[t][2 * u],     af[t], bf[u][0], bf[u][2]);
                    hmma(acc[t][2 * u + 1], af[t], bf[u][1], bf[u][3]);
                }
        }
    }

    // epilogue: += W, write fp16 into TILED+swizzled weff layout
    const int r0 = lane >> 2, c0 = (lane & 3) * 2;
    #pragma unroll
    for (int t = 0; t < 4; ++t) {
        #pragma unroll
        for (int h = 0; h < 2; ++h) {
            int o = m0 + wm * 64 + t * 16 + h * 8 + r0;
            #pragma unroll
            for (int j = 0; j < 4; ++j) {
                int i = n0 + wn * 32 + j * 8 + c0;
                const float* wr = W + (size_t)o * DIN + i;
                __half2 hv = __floats2half2_rn(acc[t][j][h * 2 + 0] + wr[0],
                                               acc[t][j][h * 2 + 1] + wr[1]);
                size_t byte = (size_t)((o >> 8) * 64 + (i >> 6)) * 32768
                            + SWZ((uint32_t)((o & 255) * 128 + (i & 63) * 2));
                *(__half2*)(outp + byte) = hv;
            }
        }
    }
}

// Big GEMM: out[m,n] = xh[m,:] @ weff[n,:]^T + bias[n], fp32 out.
// 256 threads, 8 warps (2x4), warp tile 64x64 -> smem reads/chunk 256KB (was 384KB).
// BK=128 chunks: 1 A-bulk (32KB) + 1 B-bulk (64KB) per chunk, S=2 stages of 96KB.
__global__ void __launch_bounds__(256, 1)
gemm_big(const char* __restrict__ At, const char* __restrict__ Bt,
         const float* __restrict__ bias, float* __restrict__ outp)
{
    constexpr int BM = 128, BN = 256, S = 2, NCH = 32;   // BK = 128
    constexpr int ABLK = 16384, BBLK = 32768;            // per-64K-block bytes
    constexpr int ABYTES = 2 * ABLK, BBYTES = 2 * BBLK;  // per chunk: 32KB + 64KB
    constexpr int STAGE = ABYTES + BBYTES;               // 96KB

    extern __shared__ char smraw[];
    uint32_t sbase = (smem_u32(smraw) + 1023) & ~1023u;
    uint32_t mbar  = sbase;               // 2 x 8B mbarriers
    uint32_t tiles = sbase + 1024;

    const int tid = threadIdx.x, wid = tid >> 5, lane = tid & 31;
    const int wm = wid & 1, wn = wid >> 1;   // 2 x 4 warp grid, 64x64 per warp
    const int mt = blockIdx.y, nt = blockIdx.x;
    const int m0 = mt * BM, n0 = nt * BN;

    if (tid == 0) {
        #pragma unroll
        for (int s = 0; s < S; s++)
            asm volatile("mbarrier.init.shared.b64 [%0], 1;" :: "r"(mbar + s * 8) : "memory");
        asm volatile("fence.proxy.async.shared::cta;" ::: "memory");
    }
    __syncthreads();

    auto issue = [&](int p) {   // tid0 only
        uint32_t mb = mbar + (p & 1) * 8;
        uint32_t st = tiles + (p & 1) * STAGE;
        expect_tx(mb, STAGE);
        bulkcp(st,          At + (size_t)(mt * 64 + 2 * p) * ABLK, ABYTES, mb);
        bulkcp(st + ABYTES, Bt + (size_t)(nt * 64 + 2 * p) * BBLK, BBYTES, mb);
    };

    if (tid == 0) issue(0);

    float acc[4][8][4];
    #pragma unroll
    for (int t = 0; t < 4; ++t)
        #pragma unroll
        for (int j = 0; j < 8; ++j)
            #pragma unroll
            for (int q = 0; q < 4; ++q) acc[t][j][q] = 0.f;

    const int la = lane & 15, lb = lane >> 4;

    for (int c = 0; c < NCH; ++c) {
        // refill the other stage (free at c==0; else freed by last iter's syncthreads)
        if (tid == 0 && c + 1 < NCH) issue(c + 1);
        mbar_wait(mbar + (c & 1) * 8, (uint32_t)((c >> 1) & 1));

        uint32_t sA = tiles + (c & 1) * STAGE;
        uint32_t sB = sA + ABYTES;
        #pragma unroll
        for (int ks = 0; ks < 8; ++ks) {          // 8 x K16 per BK=128 chunk
            uint32_t koff = (uint32_t)((ks & 3) * 32 + lb * 16);
            uint32_t af[4][4], bf[4][4];
            #pragma unroll
            for (int t = 0; t < 4; ++t) {
                uint32_t row = (uint32_t)(wm * 64 + t * 16 + la);
                ldsm4(af[t], sA + (uint32_t)(ks >> 2) * ABLK + SWZ(row * 128 + koff));
            }
            #pragma unroll
            for (int u = 0; u < 4; ++u) {
                uint32_t row = (uint32_t)(wn * 64 + u * 16 + la);
                ldsm4(bf[u], sB + (uint32_t)(ks >> 2) * BBLK + SWZ(row * 128 + koff));
            }
            #pragma unroll
            for (int t = 0; t < 4; ++t)
                #pragma unroll
                for (int u = 0; u < 4; ++u) {
                    hmma(acc[t][2 * u],     af[t], bf[u][0], bf[u][2]);
                    hmma(acc[t][2 * u + 1], af[t], bf[u][1], bf[u][3]);
                }
        }
        __syncthreads();   // all warps done with stage c&1 before it is refilled
    }

    // epilogue: fp32 out += bias
    const int r0 = lane >> 2, c0 = (lane & 3) * 2;
    #pragma unroll
    for (int t = 0; t < 4; ++t) {
        #pragma unroll
        for (int h = 0; h < 2; ++h) {
            size_t row = (size_t)(m0 + wm * 64 + t * 16 + h * 8 + r0);
            #pragma unroll
            for (int j = 0; j < 8; ++j) {
                int col = n0 + wn * 64 + j * 8 + c0;
                float2 w;
                w.x = acc[t][j][h * 2 + 0] + bias[col];
                w.y = acc[t][j][h * 2 + 1] + bias[col + 1];
                *(float2*)(outp + row * DOUT + col) = w;
            }
        }
    }
}

extern "C" void kernel_launch(void* const* d_in, const int* in_sizes, int n_in,
                              void* d_out, int out_size) {
    (void)in_sizes; (void)n_in; (void)out_size;
    const float* x    = (const float*)d_in[0];
    const float* W    = (const float*)d_in[1];
    const float* bias = (const float*)d_in[2];
    const float* As   = (const float*)d_in[3];
    const float* Bs   = (const float*)d_in[4];
    const float* Cs   = (const float*)d_in[5];

    char *xh, *weff;
    __half *abh, *ch;
    cudaGetSymbolAddress((void**)&xh,   g_xh);
    cudaGetSymbolAddress((void**)&weff, g_weff);
    cudaGetSymbolAddress((void**)&abh,  g_abh);
    cudaGetSymbolAddress((void**)&ch,   g_ch);

    const int SMEM_WEFF = 1024 + 2 * (128 * 128 + 256 * 128);  // 99328 B
    const int SMEM_BIG  = 1024 + 2 * (32768 + 65536);          // 197632 B
    cudaFuncSetAttribute(gemm_weff,
                         cudaFuncAttributeMaxDynamicSharedMemorySize, SMEM_WEFF);
    cudaFuncSetAttribute(gemm_big,
                         cudaFuncAttributeMaxDynamicSharedMemorySize, SMEM_BIG);

    prep_ab<<<dim3(DOUT, NFAC), RANK>>>(As, Bs, abh);
    conv_c<<<(NFAC * RANK * DIN) / 256, 256>>>(Cs, ch);
    conv_x<<<(TOKENS * DIN / 8) / 256, 256>>>(x, xh);
    // W_eff (tiled+swizzled fp16) = W + abh @ ch^T
    gemm_weff<<<dim3(DIN / 256, DOUT / 128), 512, SMEM_WEFF>>>(abh, ch, W, weff);
    // out = xh @ weff^T + bias
    gemm_big<<<dim3(DOUT / 256, TOKENS / 128), 256, SMEM_BIG>>>(xh, weff, bias, (float*)d_out);
}

// round 13
// speedup vs baseline: 1.1141x; 1.0093x over previous
#include <cuda_runtime.h>
#include <cuda_fp16.h>
#include <cstdint>

#define TOKENS 8192
#define DIN    4096
#define DOUT   4096
#define NFAC   2
#define RANK   64

// scratch (static __device__ globals; no allocation)
// xh: tiled A [mt(64)][kc(64)] blocks of 16KB (128 rows x 128B, swizzled)
// weff: tiled B [nt(16)][kc(64)] blocks of 32KB (256 rows x 128B, swizzled)
__device__ char g_xh[(size_t)TOKENS * DIN * 2];
__device__ char g_weff[(size_t)DOUT * DIN * 2];
__device__ __half g_abh[(size_t)DOUT * (NFAC * RANK)];
__device__ __half g_ch[(size_t)DIN * (NFAC * RANK)];

__device__ __forceinline__ uint32_t smem_u32(const void* p) {
    uint32_t a;
    asm("{ .reg .u64 t; cvta.to.shared.u64 t, %1; cvt.u32.u64 %0, t; }" : "=r"(a) : "l"(p));
    return a;
}
__device__ __forceinline__ void cp16(uint32_t dst, const void* src) {
    asm volatile("cp.async.cg.shared.global [%0], [%1], 16;" :: "r"(dst), "l"(src) : "memory");
}
__device__ __forceinline__ void bulkcp(uint32_t dst, const void* src, uint32_t bytes, uint32_t mbar) {
    asm volatile("cp.async.bulk.shared::cluster.global.mbarrier::complete_tx::bytes "
                 "[%0], [%1], %2, [%3];"
                 :: "r"(dst), "l"(src), "r"(bytes), "r"(mbar) : "memory");
}
__device__ __forceinline__ void expect_tx(uint32_t mbar, uint32_t bytes) {
    asm volatile("mbarrier.arrive.expect_tx.shared.b64 _, [%0], %1;"
                 :: "r"(mbar), "r"(bytes) : "memory");
}
__device__ __forceinline__ void mbar_wait(uint32_t a, uint32_t parity) {
    asm volatile(
        "{\n\t.reg .pred P;\n\tW%=:\n\t"
        "mbarrier.try_wait.parity.acquire.cta.shared::cta.b64 P, [%0], %1, 0x989680;\n\t"
        "@P bra.uni D%=;\n\tbra.uni W%=;\n\tD%=:\n\t}"
        :: "r"(a), "r"(parity) : "memory");
}
#define SWZ(o) ((o) ^ (((o) >> 3) & 0x70))

__device__ __forceinline__ void ldsm4(uint32_t* r, uint32_t addr) {
    asm volatile("ldmatrix.sync.aligned.m8n8.x4.shared.b16 {%0,%1,%2,%3}, [%4];"
                 : "=r"(r[0]), "=r"(r[1]), "=r"(r[2]), "=r"(r[3]) : "r"(addr));
}
__device__ __forceinline__ void hmma(float* c, const uint32_t* a, uint32_t b0, uint32_t b1) {
    asm volatile(
        "mma.sync.aligned.m16n8k16.row.col.f32.f16.f16.f32 "
        "{%0,%1,%2,%3}, {%4,%5,%6,%7}, {%8,%9}, {%0,%1,%2,%3};"
        : "+f"(c[0]), "+f"(c[1]), "+f"(c[2]), "+f"(c[3])
        : "r"(a[0]), "r"(a[1]), "r"(a[2]), "r"(a[3]), "r"(b0), "r"(b1));
}

// Fused prep: blocks [0,2048) do abh; blocks [2048,4096) do conv_c. 256 threads.
// abh[o, f*64+k] = fp16( sum_r tanh(A[f,o,r]) * B[f,r,k] )
// ch[i, f*64+k]  = fp16( C[f,k,i] )
__global__ void prep_fused(const float* __restrict__ As, const float* __restrict__ Bs,
                           const float* __restrict__ Cs,
                           __half* __restrict__ abh, __half* __restrict__ ch) {
    int bid = blockIdx.x, tid = threadIdx.x;
    if (bid < 2048) {
        __shared__ float ta[4][RANK];
        int sub = tid >> 6, k = tid & 63;
        int idx = bid * 4 + sub;            // [0, 8192)
        int o = idx & (DOUT - 1), f = idx >> 12;
        ta[sub][k] = tanhf(As[((size_t)f * DOUT + o) * RANK + k]);
        __syncthreads();
        const float* Bf = Bs + (size_t)f * RANK * RANK;
        float acc = 0.f;
        #pragma unroll 8
        for (int r = 0; r < RANK; ++r) acc += ta[sub][r] * Bf[r * RANK + k];
        abh[(size_t)o * (NFAC * RANK) + f * RANK + k] = __float2half_rn(acc);
    } else {
        int idx = (bid - 2048) * 256 + tid;
        int i = idx & (DIN - 1);
        int fk = idx >> 12;
        ch[(size_t)i * (NFAC * RANK) + fk] = __float2half_rn(Cs[idx]);
    }
}

// x (fp32 row-major) -> xh tiled fp16: block (m>>7, i>>6), swizzled 128x128B
__global__ void conv_x(const float* __restrict__ xi, char* __restrict__ xo) {
    int idx = blockIdx.x * 256 + threadIdx.x;       // one 16B output segment each
    int m = idx >> 9, s = idx & 511, i = s << 3;
    const float4* p = (const float4*)(xi + (size_t)m * DIN + i);
    float4 a = p[0], b = p[1];
    uint4 v;
    ((__half2*)&v)[0] = __floats2half2_rn(a.x, a.y);
    ((__half2*)&v)[1] = __floats2half2_rn(a.z, a.w);
    ((__half2*)&v)[2] = __floats2half2_rn(b.x, b.y);
    ((__half2*)&v)[3] = __floats2half2_rn(b.z, b.w);
    size_t byte = (size_t)((m >> 7) * 64 + (i >> 6)) * 16384
                + SWZ((uint32_t)((m & 127) * 128 + (i & 63) * 2));
    *(uint4*)(xo + byte) = v;
}

// W_eff GEMM: weff[o,i] = W[o,i] + abh[o,:]@ch[i,:]^T, K=128. Output in TILED layout.
__global__ void __launch_bounds__(512, 1)
gemm_weff(const __half* __restrict__ A, const __half* __restrict__ B,
          const float* __restrict__ W, char* __restrict__ outp)
{
    constexpr int BM = 128, BN = 256, BK = 64, S = 2, KTOT = 128;
    constexpr int NCH = KTOT / BK;
    constexpr int ABYTES = BM * 128, BBYTES = BN * 128, STAGE = ABYTES + BBYTES;

    extern __shared__ char smraw[];
    uint32_t sbase = (smem_u32(smraw) + 1023) & ~1023u;

    const int tid = threadIdx.x, wid = tid >> 5, lane = tid & 31;
    const int wm = wid & 1, wn = wid >> 1;
    const int m0 = blockIdx.y * BM, n0 = blockIdx.x * BN;
    const __half* Ab = A + (size_t)m0 * KTOT;
    const __half* Bb = B + (size_t)n0 * KTOT;

    auto load_chunk = [&](int p) {
        uint32_t s = sbase + (p % S) * STAGE;
        const __half* Ap = Ab + p * BK;
        const __half* Bp = Bb + p * BK;
        #pragma unroll
        for (int it = 0; it < 2; ++it) {
            int idx = tid + it * 512;
            int r = idx >> 3, sg = idx & 7;
            cp16(s + SWZ((uint32_t)(r * 128 + sg * 16)), Ap + (size_t)r * KTOT + sg * 8);
        }
        #pragma unroll
        for (int it = 0; it < 4; ++it) {
            int idx = tid + it * 512;
            int r = idx >> 3, sg = idx & 7;
            cp16(s + ABYTES + SWZ((uint32_t)(r * 128 + sg * 16)),
                 Bp + (size_t)r * KTOT + sg * 8);
        }
    };

    float acc[4][4][4];
    #pragma unroll
    for (int t = 0; t < 4; ++t)
        #pragma unroll
        for (int j = 0; j < 4; ++j)
            #pragma unroll
            for (int q = 0; q < 4; ++q) acc[t][j][q] = 0.f;

    load_chunk(0);
    asm volatile("cp.async.commit_group;" ::: "memory");
    load_chunk(1);
    asm volatile("cp.async.commit_group;" ::: "memory");

    const int la = lane & 15, lb = lane >> 4;

    #pragma unroll
    for (int c = 0; c < NCH; ++c) {
        if (c < NCH - 1)
            asm volatile("cp.async.wait_group 1;" ::: "memory");
        else
            asm volatile("cp.async.wait_group 0;" ::: "memory");
        __syncthreads();
        uint32_t sA = sbase + (c % S) * STAGE;
        uint32_t sB = sA + ABYTES;
        #pragma unroll
        for (int ks = 0; ks < 4; ++ks) {
            uint32_t af[4][4], bf[2][4];
            #pragma unroll
            for (int t = 0; t < 4; ++t) {
                uint32_t row = (uint32_t)(wm * 64 + t * 16 + la);
                ldsm4(af[t], sA + SWZ(row * 128 + (uint32_t)(ks * 32 + lb * 16)));
            }
            #pragma unroll
            for (int u = 0; u < 2; ++u) {
                uint32_t row = (uint32_t)(wn * 32 + u * 16 + la);
                ldsm4(bf[u], sB + SWZ(row * 128 + (uint32_t)(ks * 32 + lb * 16)));
            }
            #pragma unroll
            for (int t = 0; t < 4; ++t)
                #pragma unroll
                for (int u = 0; u < 2; ++u) {
                    hmma(acc[t][2 * u],     af[t], bf[u][0], bf[u][2]);
                    hmma(acc[t][2 * u + 1], af[t], bf[u][1], bf[u][3]);
                }
        }
    }

    // epilogue: += W, write fp16 into TILED+swizzled weff layout
    const int r0 = lane >> 2, c0 = (lane & 3) * 2;
    #pragma unroll
    for (int t = 0; t < 4; ++t) {
        #pragma unroll
        for (int h = 0; h < 2; ++h) {
            int o = m0 + wm * 64 + t * 16 + h * 8 + r0;
            #pragma unroll
            for (int j = 0; j < 4; ++j) {
                int i = n0 + wn * 32 + j * 8 + c0;
                const float* wr = W + (size_t)o * DIN + i;
                __half2 hv = __floats2half2_rn(acc[t][j][h * 2 + 0] + wr[0],
                                               acc[t][j][h * 2 + 1] + wr[1]);
                size_t byte = (size_t)((o >> 8) * 64 + (i >> 6)) * 32768
                            + SWZ((uint32_t)((o & 255) * 128 + (i & 63) * 2));
                *(__half2*)(outp + byte) = hv;
            }
        }
    }
}

// Big GEMM: out[m,n] = xh[m,:] @ weff[n,:]^T + bias[n], fp32 out.
// 256 threads, 8 warps (2x4), warp tile 64x64. BK=128 chunks, S=2 stages of 96KB.
// Fragments double-buffered across ks iterations to hide LDS latency under HMMA.
__global__ void __launch_bounds__(256, 1)
gemm_big(const char* __restrict__ At, const char* __restrict__ Bt,
         const float* __restrict__ bias, float* __restrict__ outp)
{
    constexpr int BM = 128, BN = 256, S = 2, NCH = 32;   // BK = 128
    constexpr int ABLK = 16384, BBLK = 32768;            // per-64K-block bytes
    constexpr int ABYTES = 2 * ABLK, BBYTES = 2 * BBLK;  // per chunk: 32KB + 64KB
    constexpr int STAGE = ABYTES + BBYTES;               // 96KB

    extern __shared__ char smraw[];
    uint32_t sbase = (smem_u32(smraw) + 1023) & ~1023u;
    uint32_t mbar  = sbase;               // 2 x 8B mbarriers
    uint32_t tiles = sbase + 1024;

    const int tid = threadIdx.x, wid = tid >> 5, lane = tid & 31;
    const int wm = wid & 1, wn = wid >> 1;   // 2 x 4 warp grid, 64x64 per warp
    const int mt = blockIdx.y, nt = blockIdx.x;
    const int m0 = mt * BM, n0 = nt * BN;

    if (tid == 0) {
        #pragma unroll
        for (int s = 0; s < S; s++)
            asm volatile("mbarrier.init.shared.b64 [%0], 1;" :: "r"(mbar + s * 8) : "memory");
        asm volatile("fence.proxy.async.shared::cta;" ::: "memory");
    }
    __syncthreads();

    auto issue = [&](int p) {   // tid0 only
        uint32_t mb = mbar + (p & 1) * 8;
        uint32_t st = tiles + (p & 1) * STAGE;
        expect_tx(mb, STAGE);
        bulkcp(st,          At + (size_t)(mt * 64 + 2 * p) * ABLK, ABYTES, mb);
        bulkcp(st + ABYTES, Bt + (size_t)(nt * 64 + 2 * p) * BBLK, BBYTES, mb);
    };

    if (tid == 0) issue(0);

    float acc[4][8][4];
    #pragma unroll
    for (int t = 0; t < 4; ++t)
        #pragma unroll
        for (int j = 0; j < 8; ++j)
            #pragma unroll
            for (int q = 0; q < 4; ++q) acc[t][j][q] = 0.f;

    const int la = lane & 15, lb = lane >> 4;
    const uint32_t arow = (uint32_t)(wm * 64 + la);   // +t*16 per frag
    const uint32_t brow = (uint32_t)(wn * 64 + la);

    uint32_t af[2][4][4], bf[2][4][4];

    for (int c = 0; c < NCH; ++c) {
        // refill the other stage (free at c==0; else freed by last iter's syncthreads)
        if (tid == 0 && c + 1 < NCH) issue(c + 1);
        mbar_wait(mbar + (c & 1) * 8, (uint32_t)((c >> 1) & 1));

        uint32_t sA = tiles + (c & 1) * STAGE;
        uint32_t sB = sA + ABYTES;

        // prime ks=0 fragments into buffer 0
        {
            uint32_t koff = (uint32_t)(lb * 16);
            #pragma unroll
            for (int t = 0; t < 4; ++t)
                ldsm4(af[0][t], sA + SWZ((arow + t * 16) * 128 + koff));
            #pragma unroll
            for (int u = 0; u < 4; ++u)
                ldsm4(bf[0][u], sB + SWZ((brow + u * 16) * 128 + koff));
        }

        #pragma unroll
        for (int ks = 0; ks < 8; ++ks) {          // 8 x K16 per BK=128 chunk
            const int cur = ks & 1, nxt = cur ^ 1;
            if (ks < 7) {                          // prefetch ks+1 into other buffer
                uint32_t koff = (uint32_t)(((ks + 1) & 3) * 32 + lb * 16);
                uint32_t sa = sA + (uint32_t)((ks + 1) >> 2) * ABLK;
                uint32_t sb = sB + (uint32_t)((ks + 1) >> 2) * BBLK;
                #pragma unroll
                for (int t = 0; t < 4; ++t)
                    ldsm4(af[nxt][t], sa + SWZ((arow + t * 16) * 128 + koff));
                #pragma unroll
                for (int u = 0; u < 4; ++u)
                    ldsm4(bf[nxt][u], sb + SWZ((brow + u * 16) * 128 + koff));
            }
            #pragma unroll
            for (int t = 0; t < 4; ++t)
                #pragma unroll
                for (int u = 0; u < 4; ++u) {
                    hmma(acc[t][2 * u],     af[cur][t], bf[cur][u][0], bf[cur][u][2]);
                    hmma(acc[t][2 * u + 1], af[cur][t], bf[cur][u][1], bf[cur][u][3]);
                }
        }
        __syncthreads();   // all warps done with stage c&1 before it is refilled
    }

    // epilogue: fp32 out += bias
    const int r0 = lane >> 2, c0 = (lane & 3) * 2;
    #pragma unroll
    for (int t = 0; t < 4; ++t) {
        #pragma unroll
        for (int h = 0; h < 2; ++h) {
            size_t row = (size_t)(m0 + wm * 64 + t * 16 + h * 8 + r0);
            #pragma unroll
            for (int j = 0; j < 8; ++j) {
                int col = n0 + wn * 64 + j * 8 + c0;
                float2 w;
                w.x = acc[t][j][h * 2 + 0] + bias[col];
                w.y = acc[t][j][h * 2 + 1] + bias[col + 1];
                *(float2*)(outp + row * DOUT + col) = w;
            }
        }
    }
}

extern "C" void kernel_launch(void* const* d_in, const int* in_sizes, int n_in,
                              void* d_out, int out_size) {
    (void)in_sizes; (void)n_in; (void)out_size;
    const float* x    = (const float*)d_in[0];
    const float* W    = (const float*)d_in[1];
    const float* bias = (const float*)d_in[2];
    const float* As   = (const float*)d_in[3];
    const float* Bs   = (const float*)d_in[4];
    const float* Cs   = (const float*)d_in[5];

    char *xh, *weff;
    __half *abh, *ch;
    cudaGetSymbolAddress((void**)&xh,   g_xh);
    cudaGetSymbolAddress((void**)&weff, g_weff);
    cudaGetSymbolAddress((void**)&abh,  g_abh);
    cudaGetSymbolAddress((void**)&ch,   g_ch);

    const int SMEM_WEFF = 1024 + 2 * (128 * 128 + 256 * 128);  // 99328 B
    const int SMEM_BIG  = 1024 + 2 * (32768 + 65536);          // 197632 B
    cudaFuncSetAttribute(gemm_weff,
                         cudaFuncAttributeMaxDynamicSharedMemorySize, SMEM_WEFF);
    cudaFuncSetAttribute(gemm_big,
                         cudaFuncAttributeMaxDynamicSharedMemorySize, SMEM_BIG);

    // launch order keeps gemm_big as the 4th launch (ncu capture slot)
    prep_fused<<<4096, 256>>>(As, Bs, Cs, abh, ch);
    conv_x<<<(TOKENS * DIN / 8) / 256, 256>>>(x, xh);
    // W_eff (tiled+swizzled fp16) = W + abh @ ch^T
    gemm_weff<<<dim3(DIN / 256, DOUT / 128), 512, SMEM_WEFF>>>(abh, ch, W, weff);
    // out = xh @ weff^T + bias
    gemm_big<<<dim3(DOUT / 256, TOKENS / 128), 256, SMEM_BIG>>>(xh, weff, bias, (float*)d_out);
}

// round 14
// speedup vs baseline: 1.2730x; 1.1426x over previous
#include <cuda_runtime.h>
#include <cuda_fp16.h>
#include <cstdint>

#define TOKENS 8192
#define DIN    4096
#define DOUT   4096
#define NFAC   2
#define RANK   64

// scratch (static __device__ globals; no allocation)
// xh: tiled A [mt(64)][kc(64)] blocks of 16KB (128 rows x 128B, swizzled)
// weff: tiled B [nt(16)][kc(64)] blocks of 32KB (256 rows x 128B, swizzled)
__device__ char g_xh[(size_t)TOKENS * DIN * 2];
__device__ char g_weff[(size_t)DOUT * DIN * 2];
__device__ __half g_abh[(size_t)DOUT * (NFAC * RANK)];
__device__ __half g_ch[(size_t)DIN * (NFAC * RANK)];

__device__ __forceinline__ uint32_t smem_u32(const void* p) {
    uint32_t a;
    asm("{ .reg .u64 t; cvta.to.shared.u64 t, %1; cvt.u32.u64 %0, t; }" : "=r"(a) : "l"(p));
    return a;
}
__device__ __forceinline__ void cp16(uint32_t dst, const void* src) {
    asm volatile("cp.async.cg.shared.global [%0], [%1], 16;" :: "r"(dst), "l"(src) : "memory");
}
__device__ __forceinline__ void bulkcp(uint32_t dst, const void* src, uint32_t bytes, uint32_t mbar) {
    asm volatile("cp.async.bulk.shared::cluster.global.mbarrier::complete_tx::bytes "
                 "[%0], [%1], %2, [%3];"
                 :: "r"(dst), "l"(src), "r"(bytes), "r"(mbar) : "memory");
}
__device__ __forceinline__ void expect_tx(uint32_t mbar, uint32_t bytes) {
    asm volatile("mbarrier.arrive.expect_tx.shared.b64 _, [%0], %1;"
                 :: "r"(mbar), "r"(bytes) : "memory");
}
__device__ __forceinline__ void mbar_wait(uint32_t a, uint32_t parity) {
    asm volatile(
        "{\n\t.reg .pred P;\n\tW%=:\n\t"
        "mbarrier.try_wait.parity.acquire.cta.shared::cta.b64 P, [%0], %1, 0x989680;\n\t"
        "@P bra.uni D%=;\n\tbra.uni W%=;\n\tD%=:\n\t}"
        :: "r"(a), "r"(parity) : "memory");
}
#define SWZ(o) ((o) ^ (((o) >> 3) & 0x70))

__device__ __forceinline__ void ldsm4(uint32_t* r, uint32_t addr) {
    asm volatile("ldmatrix.sync.aligned.m8n8.x4.shared.b16 {%0,%1,%2,%3}, [%4];"
                 : "=r"(r[0]), "=r"(r[1]), "=r"(r[2]), "=r"(r[3]) : "r"(addr));
}
__device__ __forceinline__ void hmma(float* c, const uint32_t* a, uint32_t b0, uint32_t b1) {
    asm volatile(
        "mma.sync.aligned.m16n8k16.row.col.f32.f16.f16.f32 "
        "{%0,%1,%2,%3}, {%4,%5,%6,%7}, {%8,%9}, {%0,%1,%2,%3};"
        : "+f"(c[0]), "+f"(c[1]), "+f"(c[2]), "+f"(c[3])
        : "r"(a[0]), "r"(a[1]), "r"(a[2]), "r"(a[3]), "r"(b0), "r"(b1));
}

// Fused prep: blocks [0,2048) do abh; blocks [2048,4096) do conv_c. 256 threads.
__global__ void prep_fused(const float* __restrict__ As, const float* __restrict__ Bs,
                           const float* __restrict__ Cs,
                           __half* __restrict__ abh, __half* __restrict__ ch) {
    int bid = blockIdx.x, tid = threadIdx.x;
    if (bid < 2048) {
        __shared__ float ta[4][RANK];
        int sub = tid >> 6, k = tid & 63;
        int idx = bid * 4 + sub;            // [0, 8192)
        int o = idx & (DOUT - 1), f = idx >> 12;
        ta[sub][k] = tanhf(As[((size_t)f * DOUT + o) * RANK + k]);
        __syncthreads();
        const float* Bf = Bs + (size_t)f * RANK * RANK;
        float acc = 0.f;
        #pragma unroll 8
        for (int r = 0; r < RANK; ++r) acc += ta[sub][r] * Bf[r * RANK + k];
        abh[(size_t)o * (NFAC * RANK) + f * RANK + k] = __float2half_rn(acc);
    } else {
        int idx = (bid - 2048) * 256 + tid;
        int i = idx & (DIN - 1);
        int fk = idx >> 12;
        ch[(size_t)i * (NFAC * RANK) + fk] = __float2half_rn(Cs[idx]);
    }
}

// x (fp32 row-major) -> xh tiled fp16: block (m>>7, i>>6), swizzled 128x128B
__global__ void conv_x(const float* __restrict__ xi, char* __restrict__ xo) {
    int idx = blockIdx.x * 256 + threadIdx.x;       // one 16B output segment each
    int m = idx >> 9, s = idx & 511, i = s << 3;
    const float4* p = (const float4*)(xi + (size_t)m * DIN + i);
    float4 a = p[0], b = p[1];
    uint4 v;
    ((__half2*)&v)[0] = __floats2half2_rn(a.x, a.y);
    ((__half2*)&v)[1] = __floats2half2_rn(a.z, a.w);
    ((__half2*)&v)[2] = __floats2half2_rn(b.x, b.y);
    ((__half2*)&v)[3] = __floats2half2_rn(b.z, b.w);
    size_t byte = (size_t)((m >> 7) * 64 + (i >> 6)) * 16384
                + SWZ((uint32_t)((m & 127) * 128 + (i & 63) * 2));
    *(uint4*)(xo + byte) = v;
}

// W_eff GEMM: weff[o,i] = W[o,i] + abh[o,:]@ch[i,:]^T, K=128. Output in TILED layout.
__global__ void __launch_bounds__(512, 1)
gemm_weff(const __half* __restrict__ A, const __half* __restrict__ B,
          const float* __restrict__ W, char* __restrict__ outp)
{
    constexpr int BM = 128, BN = 256, BK = 64, S = 2, KTOT = 128;
    constexpr int NCH = KTOT / BK;
    constexpr int ABYTES = BM * 128, BBYTES = BN * 128, STAGE = ABYTES + BBYTES;

    extern __shared__ char smraw[];
    uint32_t sbase = (smem_u32(smraw) + 1023) & ~1023u;

    const int tid = threadIdx.x, wid = tid >> 5, lane = tid & 31;
    const int wm = wid & 1, wn = wid >> 1;
    const int m0 = blockIdx.y * BM, n0 = blockIdx.x * BN;
    const __half* Ab = A + (size_t)m0 * KTOT;
    const __half* Bb = B + (size_t)n0 * KTOT;

    auto load_chunk = [&](int p) {
        uint32_t s = sbase + (p % S) * STAGE;
        const __half* Ap = Ab + p * BK;
        const __half* Bp = Bb + p * BK;
        #pragma unroll
        for (int it = 0; it < 2; ++it) {
            int idx = tid + it * 512;
            int r = idx >> 3, sg = idx & 7;
            cp16(s + SWZ((uint32_t)(r * 128 + sg * 16)), Ap + (size_t)r * KTOT + sg * 8);
        }
        #pragma unroll
        for (int it = 0; it < 4; ++it) {
            int idx = tid + it * 512;
            int r = idx >> 3, sg = idx & 7;
            cp16(s + ABYTES + SWZ((uint32_t)(r * 128 + sg * 16)),
                 Bp + (size_t)r * KTOT + sg * 8);
        }
    };

    float acc[4][4][4];
    #pragma unroll
    for (int t = 0; t < 4; ++t)
        #pragma unroll
        for (int j = 0; j < 4; ++j)
            #pragma unroll
            for (int q = 0; q < 4; ++q) acc[t][j][q] = 0.f;

    load_chunk(0);
    asm volatile("cp.async.commit_group;" ::: "memory");
    load_chunk(1);
    asm volatile("cp.async.commit_group;" ::: "memory");

    const int la = lane & 15, lb = lane >> 4;

    #pragma unroll
    for (int c = 0; c < NCH; ++c) {
        if (c < NCH - 1)
            asm volatile("cp.async.wait_group 1;" ::: "memory");
        else
            asm volatile("cp.async.wait_group 0;" ::: "memory");
        __syncthreads();
        uint32_t sA = sbase + (c % S) * STAGE;
        uint32_t sB = sA + ABYTES;
        #pragma unroll
        for (int ks = 0; ks < 4; ++ks) {
            uint32_t af[4][4], bf[2][4];
            #pragma unroll
            for (int t = 0; t < 4; ++t) {
                uint32_t row = (uint32_t)(wm * 64 + t * 16 + la);
                ldsm4(af[t], sA + SWZ(row * 128 + (uint32_t)(ks * 32 + lb * 16)));
            }
            #pragma unroll
            for (int u = 0; u < 2; ++u) {
                uint32_t row = (uint32_t)(wn * 32 + u * 16 + la);
                ldsm4(bf[u], sB + SWZ(row * 128 + (uint32_t)(ks * 32 + lb * 16)));
            }
            #pragma unroll
            for (int t = 0; t < 4; ++t)
                #pragma unroll
                for (int u = 0; u < 2; ++u) {
                    hmma(acc[t][2 * u],     af[t], bf[u][0], bf[u][2]);
                    hmma(acc[t][2 * u + 1], af[t], bf[u][1], bf[u][3]);
                }
        }
    }

    // epilogue: += W, write fp16 into TILED+swizzled weff layout
    const int r0 = lane >> 2, c0 = (lane & 3) * 2;
    #pragma unroll
    for (int t = 0; t < 4; ++t) {
        #pragma unroll
        for (int h = 0; h < 2; ++h) {
            int o = m0 + wm * 64 + t * 16 + h * 8 + r0;
            #pragma unroll
            for (int j = 0; j < 4; ++j) {
                int i = n0 + wn * 32 + j * 8 + c0;
                const float* wr = W + (size_t)o * DIN + i;
                __half2 hv = __floats2half2_rn(acc[t][j][h * 2 + 0] + wr[0],
                                               acc[t][j][h * 2 + 1] + wr[1]);
                size_t byte = (size_t)((o >> 8) * 64 + (i >> 6)) * 32768
                            + SWZ((uint32_t)((o & 255) * 128 + (i & 63) * 2));
                *(__half2*)(outp + byte) = hv;
            }
        }
    }
}

// Big GEMM: out[m,n] = xh[m,:] @ weff[n,:]^T + bias[n], fp32 out.
// 256 threads, 8 warps (2x4), warp tile 64x64. BK=128 chunks, S=2 stages of 96KB.
// Fragments double-buffered across ks AND across chunk boundaries: the mbar wait
// for chunk c+1 and its ks0 prefetch overlap the last HMMA block of chunk c.
__global__ void __launch_bounds__(256, 1)
gemm_big(const char* __restrict__ At, const char* __restrict__ Bt,
         const float* __restrict__ bias, float* __restrict__ outp)
{
    constexpr int S = 2, NCH = 32;                       // BK = 128
    constexpr int ABLK = 16384, BBLK = 32768;            // per-64K-block bytes
    constexpr int ABYTES = 2 * ABLK, BBYTES = 2 * BBLK;  // per chunk: 32KB + 64KB
    constexpr int STAGE = ABYTES + BBYTES;               // 96KB

    extern __shared__ char smraw[];
    uint32_t sbase = (smem_u32(smraw) + 1023) & ~1023u;
    uint32_t mbar  = sbase;               // 2 x 8B mbarriers
    uint32_t tiles = sbase + 1024;

    const int tid = threadIdx.x, wid = tid >> 5, lane = tid & 31;
    const int wm = wid & 1, wn = wid >> 1;   // 2 x 4 warp grid, 64x64 per warp
    const int mt = blockIdx.y, nt = blockIdx.x;
    const int m0 = mt * 128, n0 = nt * 256;

    if (tid == 0) {
        #pragma unroll
        for (int s = 0; s < S; s++)
            asm volatile("mbarrier.init.shared.b64 [%0], 1;" :: "r"(mbar + s * 8) : "memory");
        asm volatile("fence.proxy.async.shared::cta;" ::: "memory");
    }
    __syncthreads();

    auto issue = [&](int p) {   // tid0 only
        uint32_t mb = mbar + (p & 1) * 8;
        uint32_t st = tiles + (p & 1) * STAGE;
        expect_tx(mb, STAGE);
        bulkcp(st,          At + (size_t)(mt * 64 + 2 * p) * ABLK, ABYTES, mb);
        bulkcp(st + ABYTES, Bt + (size_t)(nt * 64 + 2 * p) * BBLK, BBYTES, mb);
    };

    if (tid == 0) issue(0);

    float acc[4][8][4];
    #pragma unroll
    for (int t = 0; t < 4; ++t)
        #pragma unroll
        for (int j = 0; j < 8; ++j)
            #pragma unroll
            for (int q = 0; q < 4; ++q) acc[t][j][q] = 0.f;

    const int la = lane & 15, lb = lane >> 4;
    // per-fragment swizzle-hoisted bases: SWZ(row*128 + koff) = row*128 + (koff ^ swz)
    uint32_t abase[4], aswz[4], bbase[4], bswz[4];
    #pragma unroll
    for (int t = 0; t < 4; ++t) {
        uint32_t row = (uint32_t)(wm * 64 + t * 16 + la);
        abase[t] = row * 128;
        aswz[t]  = (abase[t] >> 3) & 0x70;
    }
    #pragma unroll
    for (int u = 0; u < 4; ++u) {
        uint32_t row = (uint32_t)(wn * 64 + u * 16 + la);
        bbase[u] = row * 128;
        bswz[u]  = (bbase[u] >> 3) & 0x70;
    }
    const uint32_t klane = (uint32_t)(lb * 16);

    uint32_t af[2][4][4], bf[2][4][4];

    // prefetch(frags, stageA, stageB, ksIndex): ksIndex in [0,8)
    auto prefetch = [&](int buf, uint32_t sA, uint32_t sB, int ksi) {
        uint32_t koff = (uint32_t)((ksi & 3) * 32) + klane;
        uint32_t sa = sA + (uint32_t)(ksi >> 2) * ABLK;
        uint32_t sb = sB + (uint32_t)(ksi >> 2) * BBLK;
        #pragma unroll
        for (int t = 0; t < 4; ++t)
            ldsm4(af[buf][t], sa + abase[t] + (koff ^ aswz[t]));
        #pragma unroll
        for (int u = 0; u < 4; ++u)
            ldsm4(bf[buf][u], sb + bbase[u] + (koff ^ bswz[u]));
    };

    // wait chunk 0, prime ks0
    mbar_wait(mbar + 0, 0);
    prefetch(0, tiles, tiles + ABYTES, 0);

    for (int c = 0; c < NCH; ++c) {
        if (tid == 0 && c + 1 < NCH) issue(c + 1);   // stage freed by last chunk's sync
        uint32_t sA = tiles + (c & 1) * STAGE;
        uint32_t sB = sA + ABYTES;

        #pragma unroll
        for (int ks = 0; ks < 8; ++ks) {
            const int cur = ks & 1, nxt = cur ^ 1;
            if (ks < 7) {
                prefetch(nxt, sA, sB, ks + 1);
            } else if (c + 1 < NCH) {
                // next chunk's stage: copy was issued a full chunk ago — wait is cheap
                mbar_wait(mbar + ((c + 1) & 1) * 8, (uint32_t)(((c + 1) >> 1) & 1));
                uint32_t nA = tiles + ((c + 1) & 1) * STAGE;
                prefetch(nxt, nA, nA + ABYTES, 0);
            }
            #pragma unroll
            for (int t = 0; t < 4; ++t)
                #pragma unroll
                for (int u = 0; u < 4; ++u) {
                    hmma(acc[t][2 * u],     af[cur][t], bf[cur][u][0], bf[cur][u][2]);
                    hmma(acc[t][2 * u + 1], af[cur][t], bf[cur][u][1], bf[cur][u][3]);
                }
        }
        __syncthreads();   // all warps done with stage c&1 before it is refilled
    }

    // epilogue: fp32 out += bias
    const int r0 = lane >> 2, c0 = (lane & 3) * 2;
    #pragma unroll
    for (int t = 0; t < 4; ++t) {
        #pragma unroll
        for (int h = 0; h < 2; ++h) {
            size_t row = (size_t)(m0 + wm * 64 + t * 16 + h * 8 + r0);
            #pragma unroll
            for (int j = 0; j < 8; ++j) {
                int col = n0 + wn * 64 + j * 8 + c0;
                float2 w;
                w.x = acc[t][j][h * 2 + 0] + bias[col];
                w.y = acc[t][j][h * 2 + 1] + bias[col + 1];
                *(float2*)(outp + row * DOUT + col) = w;
            }
        }
    }
}

extern "C" void kernel_launch(void* const* d_in, const int* in_sizes, int n_in,
                              void* d_out, int out_size) {
    (void)in_sizes; (void)n_in; (void)out_size;
    const float* x    = (const float*)d_in[0];
    const float* W    = (const float*)d_in[1];
    const float* bias = (const float*)d_in[2];
    const float* As   = (const float*)d_in[3];
    const float* Bs   = (const float*)d_in[4];
    const float* Cs   = (const float*)d_in[5];

    char *xh, *weff;
    __half *abh, *ch;
    cudaGetSymbolAddress((void**)&xh,   g_xh);
    cudaGetSymbolAddress((void**)&weff, g_weff);
    cudaGetSymbolAddress((void**)&abh,  g_abh);
    cudaGetSymbolAddress((void**)&ch,   g_ch);

    const int SMEM_WEFF = 1024 + 2 * (128 * 128 + 256 * 128);  // 99328 B
    const int SMEM_BIG  = 1024 + 2 * (32768 + 65536);          // 197632 B
    cudaFuncSetAttribute(gemm_weff,
                         cudaFuncAttributeMaxDynamicSharedMemorySize, SMEM_WEFF);
    cudaFuncSetAttribute(gemm_big,
                         cudaFuncAttributeMaxDynamicSharedMemorySize, SMEM_BIG);

    // launch order keeps gemm_big as the 4th launch (ncu capture slot)
    prep_fused<<<4096, 256>>>(As, Bs, Cs, abh, ch);
    conv_x<<<(TOKENS * DIN / 8) / 256, 256>>>(x, xh);
    // W_eff (tiled+swizzled fp16) = W + abh @ ch^T
    gemm_weff<<<dim3(DIN / 256, DOUT / 128), 512, SMEM_WEFF>>>(abh, ch, W, weff);
    // out = xh @ weff^T + bias
    gemm_big<<<dim3(DOUT / 256, TOKENS / 128), 256, SMEM_BIG>>>(xh, weff, bias, (float*)d_out);
}

// round 16
// speedup vs baseline: 1.3121x; 1.0307x over previous
#include <cuda_runtime.h>
#include <cuda_fp16.h>
#include <cstdint>

#define TOKENS 8192
#define DIN    4096
#define DOUT   4096
#define NFAC   2
#define RANK   64

// scratch (static __device__ globals; no allocation)
// xh: tiled A [mt(64)][kc(64)] blocks of 16KB (128 rows x 128B, swizzled)
// weff: tiled B [nt(16)][kc(64)] blocks of 32KB (256 rows x 128B, swizzled)
__device__ char g_xh[(size_t)TOKENS * DIN * 2];
__device__ char g_weff[(size_t)DOUT * DIN * 2];
__device__ __half g_abh[(size_t)DOUT * (NFAC * RANK)];
__device__ __half g_ch[(size_t)DIN * (NFAC * RANK)];

__device__ __forceinline__ uint32_t smem_u32(const void* p) {
    uint32_t a;
    asm("{ .reg .u64 t; cvta.to.shared.u64 t, %1; cvt.u32.u64 %0, t; }" : "=r"(a) : "l"(p));
    return a;
}
__device__ __forceinline__ void cp16(uint32_t dst, const void* src) {
    asm volatile("cp.async.cg.shared.global [%0], [%1], 16;" :: "r"(dst), "l"(src) : "memory");
}
__device__ __forceinline__ void bulkcp(uint32_t dst, const void* src, uint32_t bytes, uint32_t mbar) {
    asm volatile("cp.async.bulk.shared::cluster.global.mbarrier::complete_tx::bytes "
                 "[%0], [%1], %2, [%3];"
                 :: "r"(dst), "l"(src), "r"(bytes), "r"(mbar) : "memory");
}
__device__ __forceinline__ void expect_tx(uint32_t mbar, uint32_t bytes) {
    asm volatile("mbarrier.arrive.expect_tx.shared.b64 _, [%0], %1;"
                 :: "r"(mbar), "r"(bytes) : "memory");
}
__device__ __forceinline__ void mbar_wait(uint32_t a, uint32_t parity) {
    asm volatile(
        "{\n\t.reg .pred P;\n\tW%=:\n\t"
        "mbarrier.try_wait.parity.acquire.cta.shared::cta.b64 P, [%0], %1, 0x989680;\n\t"
        "@P bra.uni D%=;\n\tbra.uni W%=;\n\tD%=:\n\t}"
        :: "r"(a), "r"(parity) : "memory");
}
#define SWZ(o) ((o) ^ (((o) >> 3) & 0x70))

__device__ __forceinline__ void ldsm4(uint32_t* r, uint32_t addr) {
    asm volatile("ldmatrix.sync.aligned.m8n8.x4.shared.b16 {%0,%1,%2,%3}, [%4];"
                 : "=r"(r[0]), "=r"(r[1]), "=r"(r[2]), "=r"(r[3]) : "r"(addr));
}
__device__ __forceinline__ void hmma(float* c, const uint32_t* a, uint32_t b0, uint32_t b1) {
    asm volatile(
        "mma.sync.aligned.m16n8k16.row.col.f32.f16.f16.f32 "
        "{%0,%1,%2,%3}, {%4,%5,%6,%7}, {%8,%9}, {%0,%1,%2,%3};"
        : "+f"(c[0]), "+f"(c[1]), "+f"(c[2]), "+f"(c[3])
        : "r"(a[0]), "r"(a[1]), "r"(a[2]), "r"(a[3]), "r"(b0), "r"(b1));
}

// Fused prep: blocks [0,2048) do abh; blocks [2048,4096) do conv_c. 256 threads.
__global__ void prep_fused(const float* __restrict__ As, const float* __restrict__ Bs,
                           const float* __restrict__ Cs,
                           __half* __restrict__ abh, __half* __restrict__ ch) {
    int bid = blockIdx.x, tid = threadIdx.x;
    if (bid < 2048) {
        __shared__ float ta[4][RANK];
        int sub = tid >> 6, k = tid & 63;
        int idx = bid * 4 + sub;            // [0, 8192)
        int o = idx & (DOUT - 1), f = idx >> 12;
        ta[sub][k] = tanhf(As[((size_t)f * DOUT + o) * RANK + k]);
        __syncthreads();
        const float* Bf = Bs + (size_t)f * RANK * RANK;
        float acc = 0.f;
        #pragma unroll 8
        for (int r = 0; r < RANK; ++r) acc += ta[sub][r] * Bf[r * RANK + k];
        abh[(size_t)o * (NFAC * RANK) + f * RANK + k] = __float2half_rn(acc);
    } else {
        int idx = (bid - 2048) * 256 + tid;
        int i = idx & (DIN - 1);
        int fk = idx >> 12;
        ch[(size_t)i * (NFAC * RANK) + fk] = __float2half_rn(Cs[idx]);
    }
}

// x (fp32 row-major) -> xh tiled fp16: block (m>>7, i>>6), swizzled 128x128B
__global__ void conv_x(const float* __restrict__ xi, char* __restrict__ xo) {
    int idx = blockIdx.x * 256 + threadIdx.x;       // one 16B output segment each
    int m = idx >> 9, s = idx & 511, i = s << 3;
    const float4* p = (const float4*)(xi + (size_t)m * DIN + i);
    float4 a = p[0], b = p[1];
    uint4 v;
    ((__half2*)&v)[0] = __floats2half2_rn(a.x, a.y);
    ((__half2*)&v)[1] = __floats2half2_rn(a.z, a.w);
    ((__half2*)&v)[2] = __floats2half2_rn(b.x, b.y);
    ((__half2*)&v)[3] = __floats2half2_rn(b.z, b.w);
    size_t byte = (size_t)((m >> 7) * 64 + (i >> 6)) * 16384
                + SWZ((uint32_t)((m & 127) * 128 + (i & 63) * 2));
    *(uint4*)(xo + byte) = v;
}

// W_eff GEMM: weff[o,i] = W[o,i] + abh[o,:]@ch[i,:]^T, K=128. Output in TILED layout.
__global__ void __launch_bounds__(512, 1)
gemm_weff(const __half* __restrict__ A, const __half* __restrict__ B,
          const float* __restrict__ W, char* __restrict__ outp)
{
    constexpr int BM = 128, BN = 256, BK = 64, S = 2, KTOT = 128;
    constexpr int NCH = KTOT / BK;
    constexpr int ABYTES = BM * 128, BBYTES = BN * 128, STAGE = ABYTES + BBYTES;

    extern __shared__ char smraw[];
    uint32_t sbase = (smem_u32(smraw) + 1023) & ~1023u;

    const int tid = threadIdx.x, wid = tid >> 5, lane = tid & 31;
    const int wm = wid & 1, wn = wid >> 1;
    const int m0 = blockIdx.y * BM, n0 = blockIdx.x * BN;
    const __half* Ab = A + (size_t)m0 * KTOT;
    const __half* Bb = B + (size_t)n0 * KTOT;

    auto load_chunk = [&](int p) {
        uint32_t s = sbase + (p % S) * STAGE;
        const __half* Ap = Ab + p * BK;
        const __half* Bp = Bb + p * BK;
        #pragma unroll
        for (int it = 0; it < 2; ++it) {
            int idx = tid + it * 512;
            int r = idx >> 3, sg = idx & 7;
            cp16(s + SWZ((uint32_t)(r * 128 + sg * 16)), Ap + (size_t)r * KTOT + sg * 8);
        }
        #pragma unroll
        for (int it = 0; it < 4; ++it) {
            int idx = tid + it * 512;
            int r = idx >> 3, sg = idx & 7;
            cp16(s + ABYTES + SWZ((uint32_t)(r * 128 + sg * 16)),
                 Bp + (size_t)r * KTOT + sg * 8);
        }
    };

    float acc[4][4][4];
    #pragma unroll
    for (int t = 0; t < 4; ++t)
        #pragma unroll
        for (int j = 0; j < 4; ++j)
            #pragma unroll
            for (int q = 0; q < 4; ++q) acc[t][j][q] = 0.f;

    load_chunk(0);
    asm volatile("cp.async.commit_group;" ::: "memory");
    load_chunk(1);
    asm volatile("cp.async.commit_group;" ::: "memory");

    const int la = lane & 15, lb = lane >> 4;

    #pragma unroll
    for (int c = 0; c < NCH; ++c) {
        if (c < NCH - 1)
            asm volatile("cp.async.wait_group 1;" ::: "memory");
        else
            asm volatile("cp.async.wait_group 0;" ::: "memory");
        __syncthreads();
        uint32_t sA = sbase + (c % S) * STAGE;
        uint32_t sB = sA + ABYTES;
        #pragma unroll
        for (int ks = 0; ks < 4; ++ks) {
            uint32_t af[4][4], bf[2][4];
            #pragma unroll
            for (int t = 0; t < 4; ++t) {
                uint32_t row = (uint32_t)(wm * 64 + t * 16 + la);
                ldsm4(af[t], sA + SWZ(row * 128 + (uint32_t)(ks * 32 + lb * 16)));
            }
            #pragma unroll
            for (int u = 0; u < 2; ++u) {
                uint32_t row = (uint32_t)(wn * 32 + u * 16 + la);
                ldsm4(bf[u], sB + SWZ(row * 128 + (uint32_t)(ks * 32 + lb * 16)));
            }
            #pragma unroll
            for (int t = 0; t < 4; ++t)
                #pragma unroll
                for (int u = 0; u < 2; ++u) {
                    hmma(acc[t][2 * u],     af[t], bf[u][0], bf[u][2]);
                    hmma(acc[t][2 * u + 1], af[t], bf[u][1], bf[u][3]);
                }
        }
    }

    // epilogue: += W, write fp16 into TILED+swizzled weff layout
    const int r0 = lane >> 2, c0 = (lane & 3) * 2;
    #pragma unroll
    for (int t = 0; t < 4; ++t) {
        #pragma unroll
        for (int h = 0; h < 2; ++h) {
            int o = m0 + wm * 64 + t * 16 + h * 8 + r0;
            #pragma unroll
            for (int j = 0; j < 4; ++j) {
                int i = n0 + wn * 32 + j * 8 + c0;
                const float* wr = W + (size_t)o * DIN + i;
                __half2 hv = __floats2half2_rn(acc[t][j][h * 2 + 0] + wr[0],
                                               acc[t][j][h * 2 + 1] + wr[1]);
                size_t byte = (size_t)((o >> 8) * 64 + (i >> 6)) * 32768
                            + SWZ((uint32_t)((o & 255) * 128 + (i & 63) * 2));
                *(__half2*)(outp + byte) = hv;
            }
        }
    }
}

// Big GEMM (persistent): out[m,n] = xh[m,:] @ weff[n,:]^T + bias[n], fp32 out.
// grid = nSM CTAs, each walks tiles T = bid, bid+nSM, ... The S=2 bulk-copy
// pipeline and fragment double-buffering run CONTINUOUSLY across tile
// boundaries (global chunk counter g gives stage g&1, parity (g>>1)&1).
// Plain __syncthreads() per chunk (provably deadlock-free).
__global__ void __launch_bounds__(256, 1)
gemm_big(const char* __restrict__ At, const char* __restrict__ Bt,
         const float* __restrict__ bias, float* __restrict__ outp, int nsm)
{
    constexpr int NCH = 32;                              // BK = 128
    constexpr int ABLK = 16384, BBLK = 32768;            // per-64K-block bytes
    constexpr int ABYTES = 2 * ABLK, BBYTES = 2 * BBLK;  // per chunk: 32KB + 64KB
    constexpr int STAGE = ABYTES + BBYTES;               // 96KB
    constexpr int NTILES = (DOUT / 256) * (TOKENS / 128); // 1024 (nt 16 x mt 64)

    extern __shared__ char smraw[];
    uint32_t sbase = (smem_u32(smraw) + 1023) & ~1023u;
    uint32_t mbar  = sbase;               // 2 x 8B mbarriers
    uint32_t tiles = sbase + 1024;

    const int tid = threadIdx.x, wid = tid >> 5, lane = tid & 31;
    const int wm = wid & 1, wn = wid >> 1;   // 2 x 4 warp grid, 64x64 per warp

    if (tid == 0) {
        asm volatile("mbarrier.init.shared.b64 [%0], 1;" :: "r"(mbar) : "memory");
        asm volatile("mbarrier.init.shared.b64 [%0], 1;" :: "r"(mbar + 8) : "memory");
        asm volatile("fence.proxy.async.shared::cta;" ::: "memory");
    }
    __syncthreads();

    const int bid = blockIdx.x;
    if (bid >= NTILES) return;
    const int nIter = (NTILES - bid + nsm - 1) / nsm;    // tiles for this CTA
    const int totalCh = nIter * NCH;
    int curT = bid;
    int mt = curT >> 4, nt = curT & 15;

    auto issue = [&](int gg, int tmt, int tnt, int cc) {   // tid0 only
        uint32_t mb = mbar + (gg & 1) * 8;
        uint32_t st = tiles + (gg & 1) * STAGE;
        expect_tx(mb, STAGE);
        bulkcp(st,          At + (size_t)(tmt * 64 + 2 * cc) * ABLK, ABYTES, mb);
        bulkcp(st + ABYTES, Bt + (size_t)(tnt * 64 + 2 * cc) * BBLK, BBYTES, mb);
    };

    const int la = lane & 15, lb = lane >> 4;
    // per-fragment swizzle-hoisted bases: SWZ(row*128 + koff) = row*128 + (koff ^ swz)
    uint32_t abase[4], aswz[4], bbase[4], bswz[4];
    #pragma unroll
    for (int t = 0; t < 4; ++t) {
        uint32_t row = (uint32_t)(wm * 64 + t * 16 + la);
        abase[t] = row * 128;
        aswz[t]  = (abase[t] >> 3) & 0x70;
    }
    #pragma unroll
    for (int u = 0; u < 4; ++u) {
        uint32_t row = (uint32_t)(wn * 64 + u * 16 + la);
        bbase[u] = row * 128;
        bswz[u]  = (bbase[u] >> 3) & 0x70;
    }
    const uint32_t klane = (uint32_t)(lb * 16);

    uint32_t af[2][4][4], bf[2][4][4];

    auto prefetch = [&](int buf, uint32_t sA, uint32_t sB, int ksi) {
        uint32_t koff = (uint32_t)((ksi & 3) * 32) + klane;
        uint32_t sa = sA + (uint32_t)(ksi >> 2) * ABLK;
        uint32_t sb = sB + (uint32_t)(ksi >> 2) * BBLK;
        #pragma unroll
        for (int t = 0; t < 4; ++t)
            ldsm4(af[buf][t], sa + abase[t] + (koff ^ aswz[t]));
        #pragma unroll
        for (int u = 0; u < 4; ++u)
            ldsm4(bf[buf][u], sb + bbase[u] + (koff ^ bswz[u]));
    };

    float acc[4][8][4];

    // pipeline prologue: chunk 0 of first tile
    if (tid == 0) issue(0, mt, nt, 0);
    mbar_wait(mbar, 0);
    prefetch(0, tiles, tiles + ABYTES, 0);

    int g = 0;
    for (int it = 0; it < nIter; ++it) {
        #pragma unroll
        for (int t = 0; t < 4; ++t)
            #pragma unroll
            for (int j = 0; j < 8; ++j)
                #pragma unroll
                for (int q = 0; q < 4; ++q) acc[t][j][q] = 0.f;

        const int nxtT = curT + nsm;
        const int mtn = nxtT >> 4, ntn = nxtT & 15;

        for (int c = 0; c < NCH; ++c, ++g) {
            if (tid == 0 && g + 1 < totalCh) {
                if (c + 1 < NCH) issue(g + 1, mt, nt, c + 1);
                else             issue(g + 1, mtn, ntn, 0);
            }
            uint32_t sA = tiles + (g & 1) * STAGE;
            uint32_t sB = sA + ABYTES;

            #pragma unroll
            for (int ks = 0; ks < 8; ++ks) {
                const int cur = ks & 1, nxt = cur ^ 1;
                if (ks < 7) {
                    prefetch(nxt, sA, sB, ks + 1);
                } else if (g + 1 < totalCh) {
                    mbar_wait(mbar + ((g + 1) & 1) * 8, (uint32_t)(((g + 1) >> 1) & 1));
                    uint32_t nA = tiles + ((g + 1) & 1) * STAGE;
                    prefetch(nxt, nA, nA + ABYTES, 0);
                }
                #pragma unroll
                for (int t = 0; t < 4; ++t)
                    #pragma unroll
                    for (int u = 0; u < 4; ++u) {
                        hmma(acc[t][2 * u],     af[cur][t], bf[cur][u][0], bf[cur][u][2]);
                        hmma(acc[t][2 * u + 1], af[cur][t], bf[cur][u][1], bf[cur][u][3]);
                    }
            }
            __syncthreads();   // stage g&1 free before tid0 refills it next chunk
        }

        // epilogue for this tile (overlaps with next tile's in-flight copies)
        const int m0 = mt * 128, n0 = nt * 256;
        const int r0 = lane >> 2, c0 = (lane & 3) * 2;
        #pragma unroll
        for (int t = 0; t < 4; ++t) {
            #pragma unroll
            for (int h = 0; h < 2; ++h) {
                size_t row = (size_t)(m0 + wm * 64 + t * 16 + h * 8 + r0);
                #pragma unroll
                for (int j = 0; j < 8; ++j) {
                    int col = n0 + wn * 64 + j * 8 + c0;
                    float2 w;
                    w.x = acc[t][j][h * 2 + 0] + bias[col];
                    w.y = acc[t][j][h * 2 + 1] + bias[col + 1];
                    *(float2*)(outp + row * DOUT + col) = w;
                }
            }
        }

        curT = nxtT; mt = mtn; nt = ntn;
    }
}

extern "C" void kernel_launch(void* const* d_in, const int* in_sizes, int n_in,
                              void* d_out, int out_size) {
    (void)in_sizes; (void)n_in; (void)out_size;
    const float* x    = (const float*)d_in[0];
    const float* W    = (const float*)d_in[1];
    const float* bias = (const float*)d_in[2];
    const float* As   = (const float*)d_in[3];
    const float* Bs   = (const float*)d_in[4];
    const float* Cs   = (const float*)d_in[5];

    char *xh, *weff;
    __half *abh, *ch;
    cudaGetSymbolAddress((void**)&xh,   g_xh);
    cudaGetSymbolAddress((void**)&weff, g_weff);
    cudaGetSymbolAddress((void**)&abh,  g_abh);
    cudaGetSymbolAddress((void**)&ch,   g_ch);

    int dev = 0, nsm = 148;
    cudaGetDevice(&dev);
    cudaDeviceGetAttribute(&nsm, cudaDevAttrMultiProcessorCount, dev);

    const int SMEM_WEFF = 1024 + 2 * (128 * 128 + 256 * 128);  // 99328 B
    const int SMEM_BIG  = 1024 + 2 * (32768 + 65536);          // 197632 B
    cudaFuncSetAttribute(gemm_weff,
                         cudaFuncAttributeMaxDynamicSharedMemorySize, SMEM_WEFF);
    cudaFuncSetAttribute(gemm_big,
                         cudaFuncAttributeMaxDynamicSharedMemorySize, SMEM_BIG);

    // launch order keeps gemm_big as the 4th launch (ncu capture slot)
    prep_fused<<<4096, 256>>>(As, Bs, Cs, abh, ch);
    conv_x<<<(TOKENS * DIN / 8) / 256, 256>>>(x, xh);
    // W_eff (tiled+swizzled fp16) = W + abh @ ch^T
    gemm_weff<<<dim3(DIN / 256, DOUT / 128), 512, SMEM_WEFF>>>(abh, ch, W, weff);
    // out = xh @ weff^T + bias  (persistent)
    gemm_big<<<nsm, 256, SMEM_BIG>>>(xh, weff, bias, (float*)d_out, nsm);
}